// round 4
// baseline (speedup 1.0000x reference)
#include <cuda_runtime.h>
#include <cuda_bf16.h>
#include <cstdint>

#define N_ROWS 4096
#define D_DIM  512
#define NUM_CL 512
#define MARGIN 0.3f
#define NCH    8

// ---------------- device scratch ----------------
__device__ float    g_sq[N_ROWS];
__device__ unsigned g_ap[N_ROWS];          // max intra-class dist^2 (bits)
__device__ unsigned g_an[N_ROWS];          // min inter-class dist^2 (bits)
__device__ float    g_cp[N_ROWS];
__device__ float    g_cn[N_ROWS];
__device__ float    g_csum[NUM_CL * D_DIM];
__device__ int      g_ccnt[NUM_CL];
__device__ float    g_tot[D_DIM];
__device__ float    g_cc;
__device__ __align__(16) __nv_bfloat16 g_xb[N_ROWS * D_DIM];
__device__ float    g_cspart[NCH][NUM_CL][D_DIM];
__device__ int      g_ccnt_part[NCH][NUM_CL];

// ---------------- helpers ----------------
__device__ __forceinline__ uint32_t smem_u32(const void* p) {
    uint32_t a;
    asm("{ .reg .u64 t; cvta.to.shared.u64 t, %1; cvt.u32.u64 %0, t; }" : "=r"(a) : "l"(p));
    return a;
}
__device__ __forceinline__ float blockReduceSum(float v, float* sh) {
    int tid = threadIdx.x;
    #pragma unroll
    for (int o = 16; o; o >>= 1) v += __shfl_down_sync(0xffffffffu, v, o);
    __syncthreads();
    if ((tid & 31) == 0) sh[tid >> 5] = v;
    __syncthreads();
    int nw = (blockDim.x + 31) >> 5;
    if (tid < 32) {
        v = (tid < nw) ? sh[tid] : 0.f;
        #pragma unroll
        for (int o = 16; o; o >>= 1) v += __shfl_down_sync(0xffffffffu, v, o);
    }
    return v;
}

// ---------------- prep kernels ----------------
__global__ void init_kernel() {
    int i = blockIdx.x * blockDim.x + threadIdx.x;
    if (i < N_ROWS) { g_ap[i] = 0u; g_an[i] = 0x7f800000u; }
    if (i == 0) g_cc = 0.f;
}

// fused: fp32 -> bf16 conversion + squared norms. one block (128 thr) per row
__global__ void convsq_kernel(const float* __restrict__ X) {
    __shared__ float sh[4];
    int r = blockIdx.x, t = threadIdx.x;
    const float4 v = *(const float4*)&X[(size_t)r * D_DIM + t * 4];
    __nv_bfloat162 lo = __floats2bfloat162_rn(v.x, v.y);
    __nv_bfloat162 hi = __floats2bfloat162_rn(v.z, v.w);
    *(__nv_bfloat162*)&g_xb[(size_t)r * D_DIM + t * 4]     = lo;
    *(__nv_bfloat162*)&g_xb[(size_t)r * D_DIM + t * 4 + 2] = hi;
    float a = v.x * v.x + v.y * v.y + v.z * v.z + v.w * v.w;
    a = blockReduceSum(a, sh);
    if (t == 0) g_sq[r] = a;
}

__global__ void classsum_part(const float* __restrict__ X, const int* __restrict__ T) {
    int c = blockIdx.x, ch = blockIdx.y;
    int tid = threadIdx.x;   // 256
    float a0 = 0.f, a1 = 0.f;
    int cnt = 0;
    int r0 = ch * (N_ROWS / NCH);
    for (int r = r0; r < r0 + N_ROWS / NCH; r++) {
        if (T[r] == c) {
            cnt++;
            a0 += X[(size_t)r * D_DIM + tid];
            a1 += X[(size_t)r * D_DIM + tid + 256];
        }
    }
    g_cspart[ch][c][tid]       = a0;
    g_cspart[ch][c][tid + 256] = a1;
    if (tid == 0) g_ccnt_part[ch][c] = cnt;
}

__global__ void classsum_reduce() {
    int c = blockIdx.x, tid = threadIdx.x;  // 256
    float a0 = 0.f, a1 = 0.f;
    #pragma unroll
    for (int ch = 0; ch < NCH; ch++) {
        a0 += g_cspart[ch][c][tid];
        a1 += g_cspart[ch][c][tid + 256];
    }
    g_csum[c * D_DIM + tid]       = a0;
    g_csum[c * D_DIM + tid + 256] = a1;
    if (tid == 0) {
        int s = 0;
        #pragma unroll
        for (int ch = 0; ch < NCH; ch++) s += g_ccnt_part[ch][c];
        g_ccnt[c] = s;
    }
}

__global__ void tot_kernel() {   // grid 512, block 128
    __shared__ float sh[4];
    int d = blockIdx.x;
    float s = 0.f;
    for (int c = threadIdx.x; c < NUM_CL; c += 128) s += g_csum[c * D_DIM + d];
    s = blockReduceSum(s, sh);
    if (threadIdx.x == 0) g_tot[d] = s;
}

// ---------------- tensor-core (mma.sync) distance kernel ----------------
// 128x128 tile/CTA, 8 warps of 64x32, K chunk = 32, 4-stage cp.async pipeline,
// one __syncthreads per stage. Exact triangular launch (528 CTAs).
#define KC 32
#define STAGES (D_DIM / KC)      // 16
#define NSTG 4
#define STG_BYTES (128 * KC * 2) // 8192 per matrix per stage
#define NTILE 32                 // 4096/128

__device__ __forceinline__ void ldmx4(uint32_t& r0, uint32_t& r1, uint32_t& r2, uint32_t& r3,
                                      uint32_t addr) {
    asm volatile("ldmatrix.sync.aligned.m8n8.x4.shared.b16 {%0,%1,%2,%3}, [%4];"
                 : "=r"(r0), "=r"(r1), "=r"(r2), "=r"(r3) : "r"(addr));
}
__device__ __forceinline__ void mma_bf16(float* c, uint32_t a0, uint32_t a1, uint32_t a2,
                                         uint32_t a3, uint32_t b0, uint32_t b1) {
    asm volatile("mma.sync.aligned.m16n8k16.row.col.f32.bf16.bf16.f32 "
                 "{%0,%1,%2,%3}, {%4,%5,%6,%7}, {%8,%9}, {%0,%1,%2,%3};"
                 : "+f"(c[0]), "+f"(c[1]), "+f"(c[2]), "+f"(c[3])
                 : "r"(a0), "r"(a1), "r"(a2), "r"(a3), "r"(b0), "r"(b1));
}
#define CP16(dst, src) \
    asm volatile("cp.async.cg.shared.global [%0], [%1], 16;" :: "r"(dst), "l"(src))
#define CP_COMMIT() asm volatile("cp.async.commit_group;" ::: "memory")

__global__ void __launch_bounds__(256, 2)
dist_mma_kernel(const int* __restrict__ T) {
    extern __shared__ __align__(1024) unsigned char dsm[];   // NSTG*2*8KB = 64KB
    __shared__ float sqRs[128], sqCs[128];
    __shared__ int   tRs[128], tCs[128];
    __shared__ unsigned apS[128], anS[128], apSc[128], anSc[128];

    // triangular decode: tile t -> (by, bx), bx >= by
    const int t = blockIdx.x;
    int by = (int)((2.f * NTILE + 1.f - sqrtf((2.f * NTILE + 1.f) * (2.f * NTILE + 1.f)
                                              - 8.f * (float)t)) * 0.5f);
    while (by > 0 && (by * NTILE - (by * (by - 1)) / 2) > t) by--;
    while (((by + 1) * NTILE - ((by + 1) * by) / 2) <= t) by++;
    const int bx = by + (t - (by * NTILE - (by * (by - 1)) / 2));

    const int tid = threadIdx.x, wid = tid >> 5, lane = tid & 31;
    const int rowBase = by * 128;
    const int colBase = bx * 128;
    const int warpM = (wid >> 2) * 64;
    const int warpN = (wid & 3) * 32;

    if (tid < 128) {
        sqRs[tid] = g_sq[rowBase + tid];
        sqCs[tid] = g_sq[colBase + tid];
        tRs[tid]  = T[rowBase + tid];
        tCs[tid]  = T[colBase + tid];
        apS[tid] = 0u;  anS[tid] = 0x7f800000u;
        apSc[tid] = 0u; anSc[tid] = 0x7f800000u;
    }

    const uint32_t sbA = smem_u32(dsm);
    const uint32_t sbB = sbA + NSTG * STG_BYTES;
    const char* Xb = (const char*)g_xb;

    // loader decomposition (per thread): 2 chunks per matrix per stage
    const int lr0 = tid >> 2, lu0 = tid & 3;
    const int f1 = tid + 256;
    const int lr1 = f1 >> 2, lu1 = f1 & 3;
    const uint32_t so0 = (uint32_t)(lr0 * 64 + ((lu0 * 16) ^ (((lr0 >> 1) & 3) << 4)));
    const uint32_t so1 = (uint32_t)(lr1 * 64 + ((lu1 * 16) ^ (((lr1 >> 1) & 3) << 4)));
    const size_t gA0 = ((size_t)(rowBase + lr0) * D_DIM + lu0 * 8) * 2;
    const size_t gA1 = ((size_t)(rowBase + lr1) * D_DIM + lu1 * 8) * 2;
    const size_t gB0 = ((size_t)(colBase + lr0) * D_DIM + lu0 * 8) * 2;
    const size_t gB1 = ((size_t)(colBase + lr1) * D_DIM + lu1 * 8) * 2;

    #define ISSUE_STAGE(s_) do { \
        const uint32_t bo_ = (uint32_t)(((s_) & (NSTG - 1)) * STG_BYTES); \
        const size_t ko_ = (size_t)(s_) * KC * 2; \
        CP16(sbA + bo_ + so0, Xb + gA0 + ko_); \
        CP16(sbA + bo_ + so1, Xb + gA1 + ko_); \
        CP16(sbB + bo_ + so0, Xb + gB0 + ko_); \
        CP16(sbB + bo_ + so1, Xb + gB1 + ko_); \
        CP_COMMIT(); \
    } while (0)

    // per-lane ldmatrix address precompute
    const int aRow  = warpM + (lane & 15);
    const int aKH   = (lane >> 4) * 16;
    const uint32_t aXor = (((unsigned)aRow >> 1) & 3u) << 4;
    const int nRow  = warpN + (lane & 7) + ((lane >> 4) << 3);
    const int bKH   = ((lane >> 3) & 1) * 16;
    const uint32_t bXor = (((unsigned)nRow >> 1) & 3u) << 4;

    float acc[4][4][4];
    #pragma unroll
    for (int i = 0; i < 4; i++)
        #pragma unroll
        for (int j = 0; j < 4; j++)
            #pragma unroll
            for (int c = 0; c < 4; c++) acc[i][j][c] = 0.f;

    // prologue: stages 0..2
    ISSUE_STAGE(0);
    ISSUE_STAGE(1);
    ISSUE_STAGE(2);

    for (int s = 0; s < STAGES; s++) {
        if (s < STAGES - 2)      asm volatile("cp.async.wait_group 2;" ::: "memory");
        else if (s == STAGES - 2) asm volatile("cp.async.wait_group 1;" ::: "memory");
        else                      asm volatile("cp.async.wait_group 0;" ::: "memory");
        __syncthreads();
        if (s + 3 < STAGES) ISSUE_STAGE(s + 3);

        const uint32_t bufOff = (uint32_t)((s & (NSTG - 1)) * STG_BYTES);
        #pragma unroll
        for (int ks = 0; ks < 2; ks++) {
            uint32_t b[4][2];
            #pragma unroll
            for (int nb = 0; nb < 2; nb++) {
                uint32_t addr = sbB + bufOff + (uint32_t)((nRow + nb * 16) * 64)
                              + (uint32_t)((ks * 32 + bKH) ^ bXor);
                uint32_t q0, q1, q2, q3;
                ldmx4(q0, q1, q2, q3, addr);
                b[nb * 2][0] = q0; b[nb * 2][1] = q1;
                b[nb * 2 + 1][0] = q2; b[nb * 2 + 1][1] = q3;
            }
            #pragma unroll
            for (int mi = 0; mi < 4; mi++) {
                uint32_t addr = sbA + bufOff + (uint32_t)((aRow + mi * 16) * 64)
                              + (uint32_t)((ks * 32 + aKH) ^ aXor);
                uint32_t a0, a1, a2, a3;
                ldmx4(a0, a1, a2, a3, addr);
                #pragma unroll
                for (int nj = 0; nj < 4; nj++)
                    mma_bf16(acc[mi][nj], a0, a1, a2, a3, b[nj][0], b[nj][1]);
            }
        }
    }

    // ---- epilogue ----
    const int g = lane >> 2, q = lane & 3;
    const float INF = __int_as_float(0x7f800000);

    #pragma unroll
    for (int mi = 0; mi < 4; mi++) {
        #pragma unroll
        for (int half = 0; half < 2; half++) {
            const int row = warpM + mi * 16 + g + half * 8;
            const float sqi = sqRs[row];
            const int   ti  = tRs[row];
            float ap = 0.f, an = INF;
            #pragma unroll
            for (int nj = 0; nj < 4; nj++) {
                #pragma unroll
                for (int c = 0; c < 2; c++) {
                    const int col = warpN + nj * 8 + q * 2 + c;
                    float d2 = fmaxf(sqi + sqCs[col] - 2.f * acc[mi][nj][half * 2 + c], 1e-12f);
                    acc[mi][nj][half * 2 + c] = d2;
                    if (ti == tCs[col]) ap = fmaxf(ap, d2);
                    else                an = fminf(an, d2);
                }
            }
            ap = fmaxf(ap, __shfl_xor_sync(0xffffffffu, ap, 1));
            ap = fmaxf(ap, __shfl_xor_sync(0xffffffffu, ap, 2));
            an = fminf(an, __shfl_xor_sync(0xffffffffu, an, 1));
            an = fminf(an, __shfl_xor_sync(0xffffffffu, an, 2));
            if (q == 0) {
                atomicMax(&apS[row], __float_as_uint(ap));
                atomicMin(&anS[row], __float_as_uint(an));
            }
        }
    }
    #pragma unroll
    for (int nj = 0; nj < 4; nj++) {
        #pragma unroll
        for (int c = 0; c < 2; c++) {
            const int col = warpN + nj * 8 + q * 2 + c;
            const int tc = tCs[col];
            float ap = 0.f, an = INF;
            #pragma unroll
            for (int mi = 0; mi < 4; mi++) {
                #pragma unroll
                for (int half = 0; half < 2; half++) {
                    const int row = warpM + mi * 16 + g + half * 8;
                    float d2 = acc[mi][nj][half * 2 + c];
                    if (tRs[row] == tc) ap = fmaxf(ap, d2);
                    else                an = fminf(an, d2);
                }
            }
            ap = fmaxf(ap, __shfl_xor_sync(0xffffffffu, ap, 4));
            ap = fmaxf(ap, __shfl_xor_sync(0xffffffffu, ap, 8));
            ap = fmaxf(ap, __shfl_xor_sync(0xffffffffu, ap, 16));
            an = fminf(an, __shfl_xor_sync(0xffffffffu, an, 4));
            an = fminf(an, __shfl_xor_sync(0xffffffffu, an, 8));
            an = fminf(an, __shfl_xor_sync(0xffffffffu, an, 16));
            if (g == 0) {
                atomicMax(&apSc[col], __float_as_uint(ap));
                atomicMin(&anSc[col], __float_as_uint(an));
            }
        }
    }
    __syncthreads();
    if (tid < 128) {
        atomicMax(&g_ap[rowBase + tid], apS[tid]);
        atomicMin(&g_an[rowBase + tid], anS[tid]);
        atomicMax(&g_ap[colBase + tid], apSc[tid]);
        atomicMin(&g_an[colBase + tid], anSc[tid]);
    }
}

// ---------------- centroid / cc / final ----------------
__global__ void centroid_kernel(const float* __restrict__ X, const int* __restrict__ T) {
    __shared__ float sh[4];
    int i = blockIdx.x;
    int c = T[i];
    float cnt = (float)g_ccnt[c];
    float a1 = 0.f, a2 = 0.f;
    for (int d = threadIdx.x; d < D_DIM; d += 128) {
        float cs = g_csum[c * D_DIM + d];
        float x  = X[(size_t)i * D_DIM + d];
        float tt = g_tot[d];
        float ic = cs / cnt - x;
        float oc = (tt - cs) / ((float)N_ROWS - cnt) - x;
        a1 += ic * ic;
        a2 += oc * oc;
    }
    a1 = blockReduceSum(a1, sh);
    __syncthreads();
    a2 = blockReduceSum(a2, sh);
    if (threadIdx.x == 0) { g_cp[i] = sqrtf(a1); g_cn[i] = sqrtf(a2); }
}

__global__ void cc_kernel() {
    __shared__ float sh[4];
    int c = blockIdx.x;
    int cnt = g_ccnt[c];
    if (cnt == 0) return;
    float fc = (float)cnt;
    float a = 0.f;
    for (int d = threadIdx.x; d < D_DIM; d += 128) {
        float cs = g_csum[c * D_DIM + d];
        float diff = cs / fc - (g_tot[d] - cs) / ((float)N_ROWS - fc);
        a += diff * diff;
    }
    a = blockReduceSum(a, sh);
    if (threadIdx.x == 0) atomicAdd(&g_cc, fc * sqrtf(a));
}

__global__ void final_kernel(float* __restrict__ out) {
    __shared__ float sh[8];
    float s1 = 0.f, s2 = 0.f;
    for (int i = threadIdx.x; i < N_ROWS; i += 256) {
        float ap = sqrtf(__uint_as_float(g_ap[i]));
        float an = sqrtf(__uint_as_float(g_an[i]));
        s1 += fmaxf(ap - an + MARGIN, 0.f);
        s2 += fmaxf(g_cp[i] - g_cn[i] + MARGIN, 0.f);
    }
    s1 = blockReduceSum(s1, sh);
    __syncthreads();
    s2 = blockReduceSum(s2, sh);
    if (threadIdx.x == 0) {
        out[0] = s1 / (float)N_ROWS;
        out[1] = s2 / (float)N_ROWS;
        out[2] = -g_cc / (float)N_ROWS;
    }
}

// ---------------- entry ----------------
extern "C" void kernel_launch(void* const* d_in, const int* in_sizes, int n_in,
                              void* d_out, int out_size) {
    const float* X = (const float*)d_in[0];
    const int*   T = (const int*)d_in[1];
    float* out = (float*)d_out;

    cudaFuncSetAttribute(dist_mma_kernel,
                         cudaFuncAttributeMaxDynamicSharedMemorySize,
                         NSTG * 2 * STG_BYTES);

    init_kernel<<<(N_ROWS + 255) / 256, 256>>>();          // 0
    convsq_kernel<<<N_ROWS, 128>>>(X);                     // 1
    dim3 csg(NUM_CL, NCH);
    classsum_part<<<csg, 256>>>(X, T);                     // 2

    const int ntiles = NTILE * (NTILE + 1) / 2;            // 528
    dist_mma_kernel<<<ntiles, 256, NSTG * 2 * STG_BYTES>>>(T);   // 3 (profiled)

    classsum_reduce<<<NUM_CL, 256>>>();                    // 4
    tot_kernel<<<D_DIM, 128>>>();                          // 5
    centroid_kernel<<<N_ROWS, 128>>>(X, T);                // 6
    cc_kernel<<<NUM_CL, 128>>>();                          // 7
    final_kernel<<<1, 256>>>(out);                         // 8
}

// round 5
// speedup vs baseline: 1.7336x; 1.7336x over previous
#include <cuda_runtime.h>
#include <cuda_bf16.h>
#include <cstdint>

#define N_ROWS 4096
#define D_DIM  512
#define NUM_CL 512
#define MARGIN 0.3f

// ---------------- device scratch ----------------
__device__ float    g_sq[N_ROWS];
__device__ unsigned g_ap[N_ROWS];          // max intra-class dist^2 (bits)
__device__ unsigned g_an[N_ROWS];          // min inter-class dist^2 (bits)
__device__ float    g_cp[N_ROWS];
__device__ float    g_cn[N_ROWS];
__device__ float    g_csum[NUM_CL * D_DIM];
__device__ int      g_ccnt[NUM_CL];
__device__ float    g_tot[D_DIM];
__device__ float    g_cc;
__device__ __align__(16) __nv_bfloat16 g_xb[N_ROWS * D_DIM];

// ---------------- helpers ----------------
__device__ __forceinline__ uint32_t smem_u32(const void* p) {
    uint32_t a;
    asm("{ .reg .u64 t; cvta.to.shared.u64 t, %1; cvt.u32.u64 %0, t; }" : "=r"(a) : "l"(p));
    return a;
}
__device__ __forceinline__ float blockReduceSum(float v, float* sh) {
    int tid = threadIdx.x;
    #pragma unroll
    for (int o = 16; o; o >>= 1) v += __shfl_down_sync(0xffffffffu, v, o);
    __syncthreads();
    if ((tid & 31) == 0) sh[tid >> 5] = v;
    __syncthreads();
    int nw = (blockDim.x + 31) >> 5;
    if (tid < 32) {
        v = (tid < nw) ? sh[tid] : 0.f;
        #pragma unroll
        for (int o = 16; o; o >>= 1) v += __shfl_down_sync(0xffffffffu, v, o);
    }
    return v;
}

// ---------------- prep: init + fp32->bf16 + squared norms ----------------
__global__ void prep_kernel(const float* __restrict__ X) {
    __shared__ float sh[4];
    int r = blockIdx.x, t = threadIdx.x;   // 128 threads
    const float4 v = *(const float4*)&X[(size_t)r * D_DIM + t * 4];
    __nv_bfloat162 lo = __floats2bfloat162_rn(v.x, v.y);
    __nv_bfloat162 hi = __floats2bfloat162_rn(v.z, v.w);
    *(__nv_bfloat162*)&g_xb[(size_t)r * D_DIM + t * 4]     = lo;
    *(__nv_bfloat162*)&g_xb[(size_t)r * D_DIM + t * 4 + 2] = hi;
    float a = v.x * v.x + v.y * v.y + v.z * v.z + v.w * v.w;
    a = blockReduceSum(a, sh);
    if (t == 0) {
        g_sq[r] = a;
        g_ap[r] = 0u;
        g_an[r] = 0x7f800000u;
        if (r == 0) g_cc = 0.f;
    }
}

// one block per class (512 blocks, 256 thr): deterministic class sum + count.
// T staged in shared once, then scanned there.
__global__ void __launch_bounds__(256)
classsum_kernel(const float* __restrict__ X, const int* __restrict__ T) {
    __shared__ int sT[N_ROWS];
    const int c = blockIdx.x, tid = threadIdx.x;
    #pragma unroll
    for (int i = 0; i < N_ROWS / 256; i++) sT[tid + i * 256] = T[tid + i * 256];
    __syncthreads();

    float a0 = 0.f, a1 = 0.f;
    int cnt = 0;
    for (int r = 0; r < N_ROWS; r++) {
        if (sT[r] == c) {
            cnt++;
            a0 += X[(size_t)r * D_DIM + tid];
            a1 += X[(size_t)r * D_DIM + tid + 256];
        }
    }
    g_csum[c * D_DIM + tid]       = a0;
    g_csum[c * D_DIM + tid + 256] = a1;
    if (tid == 0) g_ccnt[c] = cnt;
}

__global__ void tot_kernel() {   // grid 512, block 128
    __shared__ float sh[4];
    int d = blockIdx.x;
    float s = 0.f;
    for (int c = threadIdx.x; c < NUM_CL; c += 128) s += g_csum[c * D_DIM + d];
    s = blockReduceSum(s, sh);
    if (threadIdx.x == 0) g_tot[d] = s;
}

// ---------------- tensor-core (mma.sync) distance kernel ----------------
#define KC 32
#define STAGES (D_DIM / KC)      // 16
#define NSTG 4
#define STG_BYTES (128 * KC * 2) // 8192 per matrix per stage
#define NTILE 32                 // 4096/128

__device__ __forceinline__ void ldmx4(uint32_t& r0, uint32_t& r1, uint32_t& r2, uint32_t& r3,
                                      uint32_t addr) {
    asm volatile("ldmatrix.sync.aligned.m8n8.x4.shared.b16 {%0,%1,%2,%3}, [%4];"
                 : "=r"(r0), "=r"(r1), "=r"(r2), "=r"(r3) : "r"(addr));
}
__device__ __forceinline__ void mma_bf16(float* c, uint32_t a0, uint32_t a1, uint32_t a2,
                                         uint32_t a3, uint32_t b0, uint32_t b1) {
    asm volatile("mma.sync.aligned.m16n8k16.row.col.f32.bf16.bf16.f32 "
                 "{%0,%1,%2,%3}, {%4,%5,%6,%7}, {%8,%9}, {%0,%1,%2,%3};"
                 : "+f"(c[0]), "+f"(c[1]), "+f"(c[2]), "+f"(c[3])
                 : "r"(a0), "r"(a1), "r"(a2), "r"(a3), "r"(b0), "r"(b1));
}
#define CP16(dst, src) \
    asm volatile("cp.async.cg.shared.global [%0], [%1], 16;" :: "r"(dst), "l"(src))
#define CP_COMMIT() asm volatile("cp.async.commit_group;" ::: "memory")

__global__ void __launch_bounds__(256, 2)
dist_mma_kernel(const int* __restrict__ T) {
    extern __shared__ __align__(1024) unsigned char dsm[];   // NSTG*2*8KB = 64KB
    __shared__ float sqRs[128], sqCs[128];
    __shared__ int   tRs[128], tCs[128];
    __shared__ unsigned apS[128], anS[128], apSc[128], anSc[128];

    // triangular decode: tile t -> (by, bx), bx >= by
    const int t = blockIdx.x;
    int by = (int)((2.f * NTILE + 1.f - sqrtf((2.f * NTILE + 1.f) * (2.f * NTILE + 1.f)
                                              - 8.f * (float)t)) * 0.5f);
    while (by > 0 && (by * NTILE - (by * (by - 1)) / 2) > t) by--;
    while (((by + 1) * NTILE - ((by + 1) * by) / 2) <= t) by++;
    const int bx = by + (t - (by * NTILE - (by * (by - 1)) / 2));

    const int tid = threadIdx.x, wid = tid >> 5, lane = tid & 31;
    const int rowBase = by * 128;
    const int colBase = bx * 128;
    const int warpM = (wid >> 2) * 64;
    const int warpN = (wid & 3) * 32;

    if (tid < 128) {
        sqRs[tid] = g_sq[rowBase + tid];
        sqCs[tid] = g_sq[colBase + tid];
        tRs[tid]  = T[rowBase + tid];
        tCs[tid]  = T[colBase + tid];
        apS[tid] = 0u;  anS[tid] = 0x7f800000u;
        apSc[tid] = 0u; anSc[tid] = 0x7f800000u;
    }

    const uint32_t sbA = smem_u32(dsm);
    const uint32_t sbB = sbA + NSTG * STG_BYTES;
    const char* Xb = (const char*)g_xb;

    const int lr0 = tid >> 2, lu0 = tid & 3;
    const int f1 = tid + 256;
    const int lr1 = f1 >> 2, lu1 = f1 & 3;
    const uint32_t so0 = (uint32_t)(lr0 * 64 + ((lu0 * 16) ^ (((lr0 >> 1) & 3) << 4)));
    const uint32_t so1 = (uint32_t)(lr1 * 64 + ((lu1 * 16) ^ (((lr1 >> 1) & 3) << 4)));
    const size_t gA0 = ((size_t)(rowBase + lr0) * D_DIM + lu0 * 8) * 2;
    const size_t gA1 = ((size_t)(rowBase + lr1) * D_DIM + lu1 * 8) * 2;
    const size_t gB0 = ((size_t)(colBase + lr0) * D_DIM + lu0 * 8) * 2;
    const size_t gB1 = ((size_t)(colBase + lr1) * D_DIM + lu1 * 8) * 2;

    #define ISSUE_STAGE(s_) do { \
        const uint32_t bo_ = (uint32_t)(((s_) & (NSTG - 1)) * STG_BYTES); \
        const size_t ko_ = (size_t)(s_) * KC * 2; \
        CP16(sbA + bo_ + so0, Xb + gA0 + ko_); \
        CP16(sbA + bo_ + so1, Xb + gA1 + ko_); \
        CP16(sbB + bo_ + so0, Xb + gB0 + ko_); \
        CP16(sbB + bo_ + so1, Xb + gB1 + ko_); \
        CP_COMMIT(); \
    } while (0)

    const int aRow  = warpM + (lane & 15);
    const int aKH   = (lane >> 4) * 16;
    const uint32_t aXor = (((unsigned)aRow >> 1) & 3u) << 4;
    const int nRow  = warpN + (lane & 7) + ((lane >> 4) << 3);
    const int bKH   = ((lane >> 3) & 1) * 16;
    const uint32_t bXor = (((unsigned)nRow >> 1) & 3u) << 4;

    float acc[4][4][4];
    #pragma unroll
    for (int i = 0; i < 4; i++)
        #pragma unroll
        for (int j = 0; j < 4; j++)
            #pragma unroll
            for (int c = 0; c < 4; c++) acc[i][j][c] = 0.f;

    ISSUE_STAGE(0);
    ISSUE_STAGE(1);
    ISSUE_STAGE(2);

    for (int s = 0; s < STAGES; s++) {
        if (s < STAGES - 2)       asm volatile("cp.async.wait_group 2;" ::: "memory");
        else if (s == STAGES - 2) asm volatile("cp.async.wait_group 1;" ::: "memory");
        else                      asm volatile("cp.async.wait_group 0;" ::: "memory");
        __syncthreads();
        if (s + 3 < STAGES) ISSUE_STAGE(s + 3);

        const uint32_t bufOff = (uint32_t)((s & (NSTG - 1)) * STG_BYTES);
        #pragma unroll
        for (int ks = 0; ks < 2; ks++) {
            uint32_t b[4][2];
            #pragma unroll
            for (int nb = 0; nb < 2; nb++) {
                uint32_t addr = sbB + bufOff + (uint32_t)((nRow + nb * 16) * 64)
                              + (uint32_t)((ks * 32 + bKH) ^ bXor);
                uint32_t q0, q1, q2, q3;
                ldmx4(q0, q1, q2, q3, addr);
                b[nb * 2][0] = q0; b[nb * 2][1] = q1;
                b[nb * 2 + 1][0] = q2; b[nb * 2 + 1][1] = q3;
            }
            #pragma unroll
            for (int mi = 0; mi < 4; mi++) {
                uint32_t addr = sbA + bufOff + (uint32_t)((aRow + mi * 16) * 64)
                              + (uint32_t)((ks * 32 + aKH) ^ aXor);
                uint32_t a0, a1, a2, a3;
                ldmx4(a0, a1, a2, a3, addr);
                #pragma unroll
                for (int nj = 0; nj < 4; nj++)
                    mma_bf16(acc[mi][nj], a0, a1, a2, a3, b[nj][0], b[nj][1]);
            }
        }
    }

    // ---- epilogue ----
    const int g = lane >> 2, q = lane & 3;
    const float INF = __int_as_float(0x7f800000);

    #pragma unroll
    for (int mi = 0; mi < 4; mi++) {
        #pragma unroll
        for (int half = 0; half < 2; half++) {
            const int row = warpM + mi * 16 + g + half * 8;
            const float sqi = sqRs[row];
            const int   ti  = tRs[row];
            float ap = 0.f, an = INF;
            #pragma unroll
            for (int nj = 0; nj < 4; nj++) {
                #pragma unroll
                for (int c = 0; c < 2; c++) {
                    const int col = warpN + nj * 8 + q * 2 + c;
                    float d2 = fmaxf(sqi + sqCs[col] - 2.f * acc[mi][nj][half * 2 + c], 1e-12f);
                    acc[mi][nj][half * 2 + c] = d2;
                    if (ti == tCs[col]) ap = fmaxf(ap, d2);
                    else                an = fminf(an, d2);
                }
            }
            ap = fmaxf(ap, __shfl_xor_sync(0xffffffffu, ap, 1));
            ap = fmaxf(ap, __shfl_xor_sync(0xffffffffu, ap, 2));
            an = fminf(an, __shfl_xor_sync(0xffffffffu, an, 1));
            an = fminf(an, __shfl_xor_sync(0xffffffffu, an, 2));
            if (q == 0) {
                atomicMax(&apS[row], __float_as_uint(ap));
                atomicMin(&anS[row], __float_as_uint(an));
            }
        }
    }
    #pragma unroll
    for (int nj = 0; nj < 4; nj++) {
        #pragma unroll
        for (int c = 0; c < 2; c++) {
            const int col = warpN + nj * 8 + q * 2 + c;
            const int tc = tCs[col];
            float ap = 0.f, an = INF;
            #pragma unroll
            for (int mi = 0; mi < 4; mi++) {
                #pragma unroll
                for (int half = 0; half < 2; half++) {
                    const int row = warpM + mi * 16 + g + half * 8;
                    float d2 = acc[mi][nj][half * 2 + c];
                    if (tRs[row] == tc) ap = fmaxf(ap, d2);
                    else                an = fminf(an, d2);
                }
            }
            ap = fmaxf(ap, __shfl_xor_sync(0xffffffffu, ap, 4));
            ap = fmaxf(ap, __shfl_xor_sync(0xffffffffu, ap, 8));
            ap = fmaxf(ap, __shfl_xor_sync(0xffffffffu, ap, 16));
            an = fminf(an, __shfl_xor_sync(0xffffffffu, an, 4));
            an = fminf(an, __shfl_xor_sync(0xffffffffu, an, 8));
            an = fminf(an, __shfl_xor_sync(0xffffffffu, an, 16));
            if (g == 0) {
                atomicMax(&apSc[col], __float_as_uint(ap));
                atomicMin(&anSc[col], __float_as_uint(an));
            }
        }
    }
    __syncthreads();
    if (tid < 128) {
        atomicMax(&g_ap[rowBase + tid], apS[tid]);
        atomicMin(&g_an[rowBase + tid], anS[tid]);
        atomicMax(&g_ap[colBase + tid], apSc[tid]);
        atomicMin(&g_an[colBase + tid], anSc[tid]);
    }
}

// ---------------- centroid / cc / final ----------------
__global__ void centroid_kernel(const float* __restrict__ X, const int* __restrict__ T) {
    __shared__ float sh[4];
    int i = blockIdx.x;
    int c = T[i];
    float cnt = (float)g_ccnt[c];
    float a1 = 0.f, a2 = 0.f;
    for (int d = threadIdx.x; d < D_DIM; d += 128) {
        float cs = g_csum[c * D_DIM + d];
        float x  = X[(size_t)i * D_DIM + d];
        float tt = g_tot[d];
        float ic = cs / cnt - x;
        float oc = (tt - cs) / ((float)N_ROWS - cnt) - x;
        a1 += ic * ic;
        a2 += oc * oc;
    }
    a1 = blockReduceSum(a1, sh);
    __syncthreads();
    a2 = blockReduceSum(a2, sh);
    if (threadIdx.x == 0) { g_cp[i] = sqrtf(a1); g_cn[i] = sqrtf(a2); }
}

__global__ void cc_kernel() {
    __shared__ float sh[4];
    int c = blockIdx.x;
    int cnt = g_ccnt[c];
    if (cnt == 0) return;
    float fc = (float)cnt;
    float a = 0.f;
    for (int d = threadIdx.x; d < D_DIM; d += 128) {
        float cs = g_csum[c * D_DIM + d];
        float diff = cs / fc - (g_tot[d] - cs) / ((float)N_ROWS - fc);
        a += diff * diff;
    }
    a = blockReduceSum(a, sh);
    if (threadIdx.x == 0) atomicAdd(&g_cc, fc * sqrtf(a));
}

__global__ void final_kernel(float* __restrict__ out) {
    __shared__ float sh[8];
    float s1 = 0.f, s2 = 0.f;
    for (int i = threadIdx.x; i < N_ROWS; i += 256) {
        float ap = sqrtf(__uint_as_float(g_ap[i]));
        float an = sqrtf(__uint_as_float(g_an[i]));
        s1 += fmaxf(ap - an + MARGIN, 0.f);
        s2 += fmaxf(g_cp[i] - g_cn[i] + MARGIN, 0.f);
    }
    s1 = blockReduceSum(s1, sh);
    __syncthreads();
    s2 = blockReduceSum(s2, sh);
    if (threadIdx.x == 0) {
        out[0] = s1 / (float)N_ROWS;
        out[1] = s2 / (float)N_ROWS;
        out[2] = -g_cc / (float)N_ROWS;
    }
}

// ---------------- entry ----------------
extern "C" void kernel_launch(void* const* d_in, const int* in_sizes, int n_in,
                              void* d_out, int out_size) {
    const float* X = (const float*)d_in[0];
    const int*   T = (const int*)d_in[1];
    float* out = (float*)d_out;

    cudaFuncSetAttribute(dist_mma_kernel,
                         cudaFuncAttributeMaxDynamicSharedMemorySize,
                         NSTG * 2 * STG_BYTES);

    prep_kernel<<<N_ROWS, 128>>>(X);                       // 0
    classsum_kernel<<<NUM_CL, 256>>>(X, T);                // 1
    tot_kernel<<<D_DIM, 128>>>();                          // 2

    const int ntiles = NTILE * (NTILE + 1) / 2;            // 528
    dist_mma_kernel<<<ntiles, 256, NSTG * 2 * STG_BYTES>>>(T);   // 3 (profiled)

    centroid_kernel<<<N_ROWS, 128>>>(X, T);                // 4
    cc_kernel<<<NUM_CL, 128>>>();                          // 5
    final_kernel<<<1, 256>>>(out);                         // 6
}

// round 6
// speedup vs baseline: 5.1520x; 2.9718x over previous
#include <cuda_runtime.h>
#include <cuda_bf16.h>
#include <cstdint>

#define N_ROWS 4096
#define D_DIM  512
#define NUM_CL 512
#define MARGIN 0.3f

// ---------------- device scratch ----------------
__device__ float    g_sq[N_ROWS];
__device__ unsigned g_ap[N_ROWS];          // max intra-class dist^2 (bits)
__device__ unsigned g_an[N_ROWS];          // min inter-class dist^2 (bits)
__device__ float    g_cp[N_ROWS];
__device__ float    g_cn[N_ROWS];
__device__ float    g_csum[NUM_CL * D_DIM];
__device__ int      g_ccnt[NUM_CL];
__device__ float    g_tot[D_DIM];
__device__ float    g_cc;
__device__ __align__(16) __nv_bfloat16 g_xb[N_ROWS * D_DIM];

// ---------------- helpers ----------------
__device__ __forceinline__ uint32_t smem_u32(const void* p) {
    uint32_t a;
    asm("{ .reg .u64 t; cvta.to.shared.u64 t, %1; cvt.u32.u64 %0, t; }" : "=r"(a) : "l"(p));
    return a;
}
__device__ __forceinline__ float blockReduceSum(float v, float* sh) {
    int tid = threadIdx.x;
    #pragma unroll
    for (int o = 16; o; o >>= 1) v += __shfl_down_sync(0xffffffffu, v, o);
    __syncthreads();
    if ((tid & 31) == 0) sh[tid >> 5] = v;
    __syncthreads();
    int nw = (blockDim.x + 31) >> 5;
    if (tid < 32) {
        v = (tid < nw) ? sh[tid] : 0.f;
        #pragma unroll
        for (int o = 16; o; o >>= 1) v += __shfl_down_sync(0xffffffffu, v, o);
    }
    return v;
}

// ---------------- prep: init + fp32->bf16 + squared norms ----------------
__global__ void prep_kernel(const float* __restrict__ X) {
    __shared__ float sh[4];
    int r = blockIdx.x, t = threadIdx.x;   // 128 threads
    const float4 v = *(const float4*)&X[(size_t)r * D_DIM + t * 4];
    __nv_bfloat162 lo = __floats2bfloat162_rn(v.x, v.y);
    __nv_bfloat162 hi = __floats2bfloat162_rn(v.z, v.w);
    *(__nv_bfloat162*)&g_xb[(size_t)r * D_DIM + t * 4]     = lo;
    *(__nv_bfloat162*)&g_xb[(size_t)r * D_DIM + t * 4 + 2] = hi;
    float a = v.x * v.x + v.y * v.y + v.z * v.z + v.w * v.w;
    a = blockReduceSum(a, sh);
    if (t == 0) {
        g_sq[r] = a;
        g_ap[r] = 0u;
        g_an[r] = 0x7f800000u;
        if (r == 0) g_cc = 0.f;
    }
}

// one block per class: bitmask membership scan (visits only matching rows).
// Deterministic: rows visited in ascending order.
__global__ void __launch_bounds__(256)
classsum_kernel(const float* __restrict__ X, const int* __restrict__ T) {
    __shared__ unsigned mask[N_ROWS / 32];   // 128 words
    const int c = blockIdx.x, tid = threadIdx.x;

    if (tid < N_ROWS / 32) mask[tid] = 0u;
    __syncthreads();
    // each thread tests 16 rows, ORs its bits in (atomicOr commutes -> deterministic)
    {
        unsigned bits = 0u;
        const int r0 = tid * 16;
        #pragma unroll
        for (int i = 0; i < 16; i++)
            bits |= (T[r0 + i] == c) ? (1u << ((r0 + i) & 31)) : 0u;
        // 16 rows of one thread span exactly half a word
        if (bits) atomicOr(&mask[r0 >> 5], bits);
    }
    __syncthreads();

    float a0 = 0.f, a1 = 0.f;
    int cnt = 0;
    #pragma unroll 4
    for (int w = 0; w < N_ROWS / 32; w++) {
        unsigned m = mask[w];
        while (m) {
            int b = __ffs(m) - 1;
            m &= m - 1;
            int r = w * 32 + b;
            cnt++;
            a0 += X[(size_t)r * D_DIM + tid];
            a1 += X[(size_t)r * D_DIM + tid + 256];
        }
    }
    g_csum[c * D_DIM + tid]       = a0;
    g_csum[c * D_DIM + tid + 256] = a1;
    if (tid == 0) g_ccnt[c] = cnt;
}

__global__ void tot_kernel() {   // grid 512, block 128
    __shared__ float sh[4];
    int d = blockIdx.x;
    float s = 0.f;
    for (int c = threadIdx.x; c < NUM_CL; c += 128) s += g_csum[c * D_DIM + d];
    s = blockReduceSum(s, sh);
    if (threadIdx.x == 0) g_tot[d] = s;
}

// ---------------- tensor-core (mma.sync) distance kernel ----------------
#define KC 32
#define STAGES (D_DIM / KC)      // 16
#define NSTG 4
#define STG_BYTES (128 * KC * 2) // 8192 per matrix per stage
#define NTILE 32                 // 4096/128

__device__ __forceinline__ void ldmx4(uint32_t& r0, uint32_t& r1, uint32_t& r2, uint32_t& r3,
                                      uint32_t addr) {
    asm volatile("ldmatrix.sync.aligned.m8n8.x4.shared.b16 {%0,%1,%2,%3}, [%4];"
                 : "=r"(r0), "=r"(r1), "=r"(r2), "=r"(r3) : "r"(addr));
}
__device__ __forceinline__ void mma_bf16(float* c, uint32_t a0, uint32_t a1, uint32_t a2,
                                         uint32_t a3, uint32_t b0, uint32_t b1) {
    asm volatile("mma.sync.aligned.m16n8k16.row.col.f32.bf16.bf16.f32 "
                 "{%0,%1,%2,%3}, {%4,%5,%6,%7}, {%8,%9}, {%0,%1,%2,%3};"
                 : "+f"(c[0]), "+f"(c[1]), "+f"(c[2]), "+f"(c[3])
                 : "r"(a0), "r"(a1), "r"(a2), "r"(a3), "r"(b0), "r"(b1));
}
#define CP16(dst, src) \
    asm volatile("cp.async.cg.shared.global [%0], [%1], 16;" :: "r"(dst), "l"(src))
#define CP_COMMIT() asm volatile("cp.async.commit_group;" ::: "memory")

__global__ void __launch_bounds__(256, 2)
dist_mma_kernel(const int* __restrict__ T) {
    extern __shared__ __align__(1024) unsigned char dsm[];   // NSTG*2*8KB = 64KB
    __shared__ float sqRs[128], sqCs[128];
    __shared__ int   tRs[128], tCs[128];
    __shared__ unsigned apS[128], anS[128], apSc[128], anSc[128];

    // triangular decode: tile t -> (by, bx), bx >= by
    const int t = blockIdx.x;
    int by = (int)((2.f * NTILE + 1.f - sqrtf((2.f * NTILE + 1.f) * (2.f * NTILE + 1.f)
                                              - 8.f * (float)t)) * 0.5f);
    while (by > 0 && (by * NTILE - (by * (by - 1)) / 2) > t) by--;
    while (((by + 1) * NTILE - ((by + 1) * by) / 2) <= t) by++;
    const int bx = by + (t - (by * NTILE - (by * (by - 1)) / 2));

    const int tid = threadIdx.x, wid = tid >> 5, lane = tid & 31;
    const int rowBase = by * 128;
    const int colBase = bx * 128;
    const int warpM = (wid >> 2) * 64;
    const int warpN = (wid & 3) * 32;

    if (tid < 128) {
        sqRs[tid] = g_sq[rowBase + tid];
        sqCs[tid] = g_sq[colBase + tid];
        tRs[tid]  = T[rowBase + tid];
        tCs[tid]  = T[colBase + tid];
        apS[tid] = 0u;  anS[tid] = 0x7f800000u;
        apSc[tid] = 0u; anSc[tid] = 0x7f800000u;
    }

    const uint32_t sbA = smem_u32(dsm);
    const uint32_t sbB = sbA + NSTG * STG_BYTES;
    const char* Xb = (const char*)g_xb;

    const int lr0 = tid >> 2, lu0 = tid & 3;
    const int f1 = tid + 256;
    const int lr1 = f1 >> 2, lu1 = f1 & 3;
    const uint32_t so0 = (uint32_t)(lr0 * 64 + ((lu0 * 16) ^ (((lr0 >> 1) & 3) << 4)));
    const uint32_t so1 = (uint32_t)(lr1 * 64 + ((lu1 * 16) ^ (((lr1 >> 1) & 3) << 4)));
    const size_t gA0 = ((size_t)(rowBase + lr0) * D_DIM + lu0 * 8) * 2;
    const size_t gA1 = ((size_t)(rowBase + lr1) * D_DIM + lu1 * 8) * 2;
    const size_t gB0 = ((size_t)(colBase + lr0) * D_DIM + lu0 * 8) * 2;
    const size_t gB1 = ((size_t)(colBase + lr1) * D_DIM + lu1 * 8) * 2;

    #define ISSUE_STAGE(s_) do { \
        const uint32_t bo_ = (uint32_t)(((s_) & (NSTG - 1)) * STG_BYTES); \
        const size_t ko_ = (size_t)(s_) * KC * 2; \
        CP16(sbA + bo_ + so0, Xb + gA0 + ko_); \
        CP16(sbA + bo_ + so1, Xb + gA1 + ko_); \
        CP16(sbB + bo_ + so0, Xb + gB0 + ko_); \
        CP16(sbB + bo_ + so1, Xb + gB1 + ko_); \
        CP_COMMIT(); \
    } while (0)

    const int aRow  = warpM + (lane & 15);
    const int aKH   = (lane >> 4) * 16;
    const uint32_t aXor = (((unsigned)aRow >> 1) & 3u) << 4;
    const int nRow  = warpN + (lane & 7) + ((lane >> 4) << 3);
    const int bKH   = ((lane >> 3) & 1) * 16;
    const uint32_t bXor = (((unsigned)nRow >> 1) & 3u) << 4;

    float acc[4][4][4];
    #pragma unroll
    for (int i = 0; i < 4; i++)
        #pragma unroll
        for (int j = 0; j < 4; j++)
            #pragma unroll
            for (int c = 0; c < 4; c++) acc[i][j][c] = 0.f;

    ISSUE_STAGE(0);
    ISSUE_STAGE(1);
    ISSUE_STAGE(2);

    for (int s = 0; s < STAGES; s++) {
        if (s < STAGES - 2)       asm volatile("cp.async.wait_group 2;" ::: "memory");
        else if (s == STAGES - 2) asm volatile("cp.async.wait_group 1;" ::: "memory");
        else                      asm volatile("cp.async.wait_group 0;" ::: "memory");
        __syncthreads();
        if (s + 3 < STAGES) ISSUE_STAGE(s + 3);

        const uint32_t bufOff = (uint32_t)((s & (NSTG - 1)) * STG_BYTES);
        #pragma unroll
        for (int ks = 0; ks < 2; ks++) {
            uint32_t b[4][2];
            #pragma unroll
            for (int nb = 0; nb < 2; nb++) {
                uint32_t addr = sbB + bufOff + (uint32_t)((nRow + nb * 16) * 64)
                              + (uint32_t)((ks * 32 + bKH) ^ bXor);
                uint32_t q0, q1, q2, q3;
                ldmx4(q0, q1, q2, q3, addr);
                b[nb * 2][0] = q0; b[nb * 2][1] = q1;
                b[nb * 2 + 1][0] = q2; b[nb * 2 + 1][1] = q3;
            }
            #pragma unroll
            for (int mi = 0; mi < 4; mi++) {
                uint32_t addr = sbA + bufOff + (uint32_t)((aRow + mi * 16) * 64)
                              + (uint32_t)((ks * 32 + aKH) ^ aXor);
                uint32_t a0, a1, a2, a3;
                ldmx4(a0, a1, a2, a3, addr);
                #pragma unroll
                for (int nj = 0; nj < 4; nj++)
                    mma_bf16(acc[mi][nj], a0, a1, a2, a3, b[nj][0], b[nj][1]);
            }
        }
    }

    // ---- epilogue ----
    const int g = lane >> 2, q = lane & 3;
    const float INF = __int_as_float(0x7f800000);

    #pragma unroll
    for (int mi = 0; mi < 4; mi++) {
        #pragma unroll
        for (int half = 0; half < 2; half++) {
            const int row = warpM + mi * 16 + g + half * 8;
            const float sqi = sqRs[row];
            const int   ti  = tRs[row];
            float ap = 0.f, an = INF;
            #pragma unroll
            for (int nj = 0; nj < 4; nj++) {
                #pragma unroll
                for (int c = 0; c < 2; c++) {
                    const int col = warpN + nj * 8 + q * 2 + c;
                    float d2 = fmaxf(sqi + sqCs[col] - 2.f * acc[mi][nj][half * 2 + c], 1e-12f);
                    acc[mi][nj][half * 2 + c] = d2;
                    if (ti == tCs[col]) ap = fmaxf(ap, d2);
                    else                an = fminf(an, d2);
                }
            }
            ap = fmaxf(ap, __shfl_xor_sync(0xffffffffu, ap, 1));
            ap = fmaxf(ap, __shfl_xor_sync(0xffffffffu, ap, 2));
            an = fminf(an, __shfl_xor_sync(0xffffffffu, an, 1));
            an = fminf(an, __shfl_xor_sync(0xffffffffu, an, 2));
            if (q == 0) {
                atomicMax(&apS[row], __float_as_uint(ap));
                atomicMin(&anS[row], __float_as_uint(an));
            }
        }
    }
    #pragma unroll
    for (int nj = 0; nj < 4; nj++) {
        #pragma unroll
        for (int c = 0; c < 2; c++) {
            const int col = warpN + nj * 8 + q * 2 + c;
            const int tc = tCs[col];
            float ap = 0.f, an = INF;
            #pragma unroll
            for (int mi = 0; mi < 4; mi++) {
                #pragma unroll
                for (int half = 0; half < 2; half++) {
                    const int row = warpM + mi * 16 + g + half * 8;
                    float d2 = acc[mi][nj][half * 2 + c];
                    if (tRs[row] == tc) ap = fmaxf(ap, d2);
                    else                an = fminf(an, d2);
                }
            }
            ap = fmaxf(ap, __shfl_xor_sync(0xffffffffu, ap, 4));
            ap = fmaxf(ap, __shfl_xor_sync(0xffffffffu, ap, 8));
            ap = fmaxf(ap, __shfl_xor_sync(0xffffffffu, ap, 16));
            an = fminf(an, __shfl_xor_sync(0xffffffffu, an, 4));
            an = fminf(an, __shfl_xor_sync(0xffffffffu, an, 8));
            an = fminf(an, __shfl_xor_sync(0xffffffffu, an, 16));
            if (g == 0) {
                atomicMax(&apSc[col], __float_as_uint(ap));
                atomicMin(&anSc[col], __float_as_uint(an));
            }
        }
    }
    __syncthreads();
    if (tid < 128) {
        atomicMax(&g_ap[rowBase + tid], apS[tid]);
        atomicMin(&g_an[rowBase + tid], anS[tid]);
        atomicMax(&g_ap[colBase + tid], apSc[tid]);
        atomicMin(&g_an[colBase + tid], anSc[tid]);
    }
}

// ---------------- centroid / cc / final ----------------
__global__ void __launch_bounds__(256)
centroid_kernel(const float* __restrict__ X, const int* __restrict__ T) {
    __shared__ float sh[8];
    int i = blockIdx.x;
    int c = T[i];
    float cnt = (float)g_ccnt[c];
    float a1 = 0.f, a2 = 0.f;
    #pragma unroll
    for (int it = 0; it < 2; it++) {
        int d = threadIdx.x + it * 256;
        float cs = g_csum[c * D_DIM + d];
        float x  = X[(size_t)i * D_DIM + d];
        float tt = g_tot[d];
        float ic = cs / cnt - x;
        float oc = (tt - cs) / ((float)N_ROWS - cnt) - x;
        a1 += ic * ic;
        a2 += oc * oc;
    }
    a1 = blockReduceSum(a1, sh);
    __syncthreads();
    a2 = blockReduceSum(a2, sh);
    if (threadIdx.x == 0) { g_cp[i] = sqrtf(a1); g_cn[i] = sqrtf(a2); }
}

__global__ void cc_kernel() {
    __shared__ float sh[4];
    int c = blockIdx.x;
    int cnt = g_ccnt[c];
    if (cnt == 0) return;
    float fc = (float)cnt;
    float a = 0.f;
    for (int d = threadIdx.x; d < D_DIM; d += 128) {
        float cs = g_csum[c * D_DIM + d];
        float diff = cs / fc - (g_tot[d] - cs) / ((float)N_ROWS - fc);
        a += diff * diff;
    }
    a = blockReduceSum(a, sh);
    if (threadIdx.x == 0) atomicAdd(&g_cc, fc * sqrtf(a));
}

__global__ void final_kernel(float* __restrict__ out) {
    __shared__ float sh[8];
    float s1 = 0.f, s2 = 0.f;
    for (int i = threadIdx.x; i < N_ROWS; i += 256) {
        float ap = sqrtf(__uint_as_float(g_ap[i]));
        float an = sqrtf(__uint_as_float(g_an[i]));
        s1 += fmaxf(ap - an + MARGIN, 0.f);
        s2 += fmaxf(g_cp[i] - g_cn[i] + MARGIN, 0.f);
    }
    s1 = blockReduceSum(s1, sh);
    __syncthreads();
    s2 = blockReduceSum(s2, sh);
    if (threadIdx.x == 0) {
        out[0] = s1 / (float)N_ROWS;
        out[1] = s2 / (float)N_ROWS;
        out[2] = -g_cc / (float)N_ROWS;
    }
}

// ---------------- entry ----------------
extern "C" void kernel_launch(void* const* d_in, const int* in_sizes, int n_in,
                              void* d_out, int out_size) {
    const float* X = (const float*)d_in[0];
    const int*   T = (const int*)d_in[1];
    float* out = (float*)d_out;

    cudaFuncSetAttribute(dist_mma_kernel,
                         cudaFuncAttributeMaxDynamicSharedMemorySize,
                         NSTG * 2 * STG_BYTES);

    prep_kernel<<<N_ROWS, 128>>>(X);                       // 0
    classsum_kernel<<<NUM_CL, 256>>>(X, T);                // 1
    tot_kernel<<<D_DIM, 128>>>();                          // 2

    const int ntiles = NTILE * (NTILE + 1) / 2;            // 528
    dist_mma_kernel<<<ntiles, 256, NSTG * 2 * STG_BYTES>>>(T);   // 3 (profiled)

    centroid_kernel<<<N_ROWS, 256>>>(X, T);                // 4
    cc_kernel<<<NUM_CL, 128>>>();                          // 5
    final_kernel<<<1, 256>>>(out);                         // 6
}

// round 7
// speedup vs baseline: 5.5882x; 1.0847x over previous
#include <cuda_runtime.h>
#include <cuda_bf16.h>
#include <cstdint>

#define N_ROWS 4096
#define D_DIM  512
#define NUM_CL 512
#define MARGIN 0.3f

// ---------------- device scratch ----------------
__device__ float    g_sq[N_ROWS];
__device__ unsigned g_ap[N_ROWS];          // max intra-class dist^2 (bits)
__device__ unsigned g_an[N_ROWS];          // min inter-class dist^2 (bits)
__device__ float    g_cp[N_ROWS];
__device__ float    g_cn[N_ROWS];
__device__ float    g_csum[NUM_CL * D_DIM];
__device__ int      g_ccnt[NUM_CL];
__device__ float    g_tot[D_DIM];
__device__ float    g_cc;
__device__ __align__(16) __nv_bfloat16 g_xb[N_ROWS * D_DIM];

// ---------------- helpers ----------------
__device__ __forceinline__ uint32_t smem_u32(const void* p) {
    uint32_t a;
    asm("{ .reg .u64 t; cvta.to.shared.u64 t, %1; cvt.u32.u64 %0, t; }" : "=r"(a) : "l"(p));
    return a;
}
__device__ __forceinline__ float blockReduceSum(float v, float* sh) {
    int tid = threadIdx.x;
    #pragma unroll
    for (int o = 16; o; o >>= 1) v += __shfl_down_sync(0xffffffffu, v, o);
    __syncthreads();
    if ((tid & 31) == 0) sh[tid >> 5] = v;
    __syncthreads();
    int nw = (blockDim.x + 31) >> 5;
    if (tid < 32) {
        v = (tid < nw) ? sh[tid] : 0.f;
        #pragma unroll
        for (int o = 16; o; o >>= 1) v += __shfl_down_sync(0xffffffffu, v, o);
    }
    return v;
}

// ---------------- prep: init + fp32->bf16 + squared norms ----------------
__global__ void prep_kernel(const float* __restrict__ X) {
    __shared__ float sh[4];
    int r = blockIdx.x, t = threadIdx.x;   // 128 threads
    const float4 v = *(const float4*)&X[(size_t)r * D_DIM + t * 4];
    __nv_bfloat162 lo = __floats2bfloat162_rn(v.x, v.y);
    __nv_bfloat162 hi = __floats2bfloat162_rn(v.z, v.w);
    *(__nv_bfloat162*)&g_xb[(size_t)r * D_DIM + t * 4]     = lo;
    *(__nv_bfloat162*)&g_xb[(size_t)r * D_DIM + t * 4 + 2] = hi;
    float a = v.x * v.x + v.y * v.y + v.z * v.z + v.w * v.w;
    a = blockReduceSum(a, sh);
    if (t == 0) {
        g_sq[r] = a;
        g_ap[r] = 0u;
        g_an[r] = 0x7f800000u;
        if (r == 0) g_cc = 0.f;
    }
}

// one block per class: bitmask membership scan (visits only matching rows).
__global__ void __launch_bounds__(256)
classsum_kernel(const float* __restrict__ X, const int* __restrict__ T) {
    __shared__ unsigned mask[N_ROWS / 32];   // 128 words
    const int c = blockIdx.x, tid = threadIdx.x;

    if (tid < N_ROWS / 32) mask[tid] = 0u;
    __syncthreads();
    {
        unsigned bits = 0u;
        const int r0 = tid * 16;
        #pragma unroll
        for (int i = 0; i < 16; i++)
            bits |= (T[r0 + i] == c) ? (1u << ((r0 + i) & 31)) : 0u;
        if (bits) atomicOr(&mask[r0 >> 5], bits);
    }
    __syncthreads();

    float a0 = 0.f, a1 = 0.f;
    int cnt = 0;
    #pragma unroll 4
    for (int w = 0; w < N_ROWS / 32; w++) {
        unsigned m = mask[w];
        while (m) {
            int b = __ffs(m) - 1;
            m &= m - 1;
            int r = w * 32 + b;
            cnt++;
            a0 += X[(size_t)r * D_DIM + tid];
            a1 += X[(size_t)r * D_DIM + tid + 256];
        }
    }
    g_csum[c * D_DIM + tid]       = a0;
    g_csum[c * D_DIM + tid + 256] = a1;
    if (tid == 0) g_ccnt[c] = cnt;
}

__global__ void tot_kernel() {   // grid 512, block 128
    __shared__ float sh[4];
    int d = blockIdx.x;
    float s = 0.f;
    for (int c = threadIdx.x; c < NUM_CL; c += 128) s += g_csum[c * D_DIM + d];
    s = blockReduceSum(s, sh);
    if (threadIdx.x == 0) g_tot[d] = s;
}

// ---------------- tensor-core (mma.sync) distance kernel ----------------
#define KC 64
#define STAGES (D_DIM / KC)      // 8
#define NSTG 3
#define STG_BYTES (128 * KC * 2) // 16384 per matrix per stage
#define NTILE 32                 // 4096/128

__device__ __forceinline__ void ldmx4(uint32_t& r0, uint32_t& r1, uint32_t& r2, uint32_t& r3,
                                      uint32_t addr) {
    asm volatile("ldmatrix.sync.aligned.m8n8.x4.shared.b16 {%0,%1,%2,%3}, [%4];"
                 : "=r"(r0), "=r"(r1), "=r"(r2), "=r"(r3) : "r"(addr));
}
__device__ __forceinline__ void mma_bf16(float* c, uint32_t a0, uint32_t a1, uint32_t a2,
                                         uint32_t a3, uint32_t b0, uint32_t b1) {
    asm volatile("mma.sync.aligned.m16n8k16.row.col.f32.bf16.bf16.f32 "
                 "{%0,%1,%2,%3}, {%4,%5,%6,%7}, {%8,%9}, {%0,%1,%2,%3};"
                 : "+f"(c[0]), "+f"(c[1]), "+f"(c[2]), "+f"(c[3])
                 : "r"(a0), "r"(a1), "r"(a2), "r"(a3), "r"(b0), "r"(b1));
}
#define CP16(dst, src) \
    asm volatile("cp.async.cg.shared.global [%0], [%1], 16;" :: "r"(dst), "l"(src))
#define CP_COMMIT() asm volatile("cp.async.commit_group;" ::: "memory")

__global__ void __launch_bounds__(256, 2)
dist_mma_kernel(const int* __restrict__ T) {
    extern __shared__ __align__(1024) unsigned char dsm[];   // NSTG*2*16KB = 96KB
    __shared__ float sqRs[128], sqCs[128];
    __shared__ int   tRs[128], tCs[128];
    __shared__ unsigned apS[128], anS[128], apSc[128], anSc[128];

    // triangular decode: tile t -> (by, bx), bx >= by
    const int t = blockIdx.x;
    int by = (int)((2.f * NTILE + 1.f - sqrtf((2.f * NTILE + 1.f) * (2.f * NTILE + 1.f)
                                              - 8.f * (float)t)) * 0.5f);
    while (by > 0 && (by * NTILE - (by * (by - 1)) / 2) > t) by--;
    while (((by + 1) * NTILE - ((by + 1) * by) / 2) <= t) by++;
    const int bx = by + (t - (by * NTILE - (by * (by - 1)) / 2));

    const int tid = threadIdx.x, wid = tid >> 5, lane = tid & 31;
    const int rowBase = by * 128;
    const int colBase = bx * 128;
    const int warpM = (wid >> 2) * 64;
    const int warpN = (wid & 3) * 32;

    if (tid < 128) {
        sqRs[tid] = g_sq[rowBase + tid];
        sqCs[tid] = g_sq[colBase + tid];
        tRs[tid]  = T[rowBase + tid];
        tCs[tid]  = T[colBase + tid];
        apS[tid] = 0u;  anS[tid] = 0x7f800000u;
        apSc[tid] = 0u; anSc[tid] = 0x7f800000u;
    }

    const uint32_t sbA = smem_u32(dsm);
    const uint32_t sbB = sbA + NSTG * STG_BYTES;
    const char* Xb = (const char*)g_xb;

    // loader: 128 rows x 128 bytes per matrix per stage; 4 chunks/thread/matrix
    uint32_t soL[4];
    size_t gAL[4], gBL[4];
    #pragma unroll
    for (int it = 0; it < 4; it++) {
        int f = tid + it * 256;          // 0..1023
        int r = f >> 3, u = f & 7;
        soL[it] = (uint32_t)(r * 128 + ((u * 16) ^ ((r & 7) << 4)));
        gAL[it] = ((size_t)(rowBase + r) * D_DIM + u * 8) * 2;
        gBL[it] = ((size_t)(colBase + r) * D_DIM + u * 8) * 2;
    }

    #define ISSUE_STAGE(s_) do { \
        const uint32_t bo_ = (uint32_t)(((s_) % NSTG) * STG_BYTES); \
        const size_t ko_ = (size_t)(s_) * (KC * 2); \
        CP16(sbA + bo_ + soL[0], Xb + gAL[0] + ko_); \
        CP16(sbA + bo_ + soL[1], Xb + gAL[1] + ko_); \
        CP16(sbA + bo_ + soL[2], Xb + gAL[2] + ko_); \
        CP16(sbA + bo_ + soL[3], Xb + gAL[3] + ko_); \
        CP16(sbB + bo_ + soL[0], Xb + gBL[0] + ko_); \
        CP16(sbB + bo_ + soL[1], Xb + gBL[1] + ko_); \
        CP16(sbB + bo_ + soL[2], Xb + gBL[2] + ko_); \
        CP16(sbB + bo_ + soL[3], Xb + gBL[3] + ko_); \
        CP_COMMIT(); \
    } while (0)

    // per-lane ldmatrix address precompute (128B row stride, SW128 atom)
    const int aRow  = warpM + (lane & 15);
    const int aKH   = (lane >> 4) * 16;
    const uint32_t aXor = ((unsigned)(aRow & 7)) << 4;
    const int nRow  = warpN + (lane & 7) + ((lane >> 4) << 3);
    const int bKH   = ((lane >> 3) & 1) * 16;
    const uint32_t bXor = ((unsigned)(nRow & 7)) << 4;

    float acc[4][4][4];
    #pragma unroll
    for (int i = 0; i < 4; i++)
        #pragma unroll
        for (int j = 0; j < 4; j++)
            #pragma unroll
            for (int c = 0; c < 4; c++) acc[i][j][c] = 0.f;

    ISSUE_STAGE(0);
    ISSUE_STAGE(1);

    for (int s = 0; s < STAGES; s++) {
        if (s < STAGES - 1) asm volatile("cp.async.wait_group 1;" ::: "memory");
        else                asm volatile("cp.async.wait_group 0;" ::: "memory");
        __syncthreads();
        if (s + 2 < STAGES) ISSUE_STAGE(s + 2);

        const uint32_t bufOff = (uint32_t)((s % NSTG) * STG_BYTES);
        #pragma unroll
        for (int ks = 0; ks < 4; ks++) {
            uint32_t b[4][2];
            #pragma unroll
            for (int nb = 0; nb < 2; nb++) {
                uint32_t addr = sbB + bufOff + (uint32_t)((nRow + nb * 16) * 128)
                              + (uint32_t)((ks * 32 + bKH) ^ bXor);
                uint32_t q0, q1, q2, q3;
                ldmx4(q0, q1, q2, q3, addr);
                b[nb * 2][0] = q0; b[nb * 2][1] = q1;
                b[nb * 2 + 1][0] = q2; b[nb * 2 + 1][1] = q3;
            }
            #pragma unroll
            for (int mi = 0; mi < 4; mi++) {
                uint32_t addr = sbA + bufOff + (uint32_t)((aRow + mi * 16) * 128)
                              + (uint32_t)((ks * 32 + aKH) ^ aXor);
                uint32_t a0, a1, a2, a3;
                ldmx4(a0, a1, a2, a3, addr);
                #pragma unroll
                for (int nj = 0; nj < 4; nj++)
                    mma_bf16(acc[mi][nj], a0, a1, a2, a3, b[nj][0], b[nj][1]);
            }
        }
    }

    // ---- epilogue ----
    const int g = lane >> 2, q = lane & 3;
    const float INF = __int_as_float(0x7f800000);

    #pragma unroll
    for (int mi = 0; mi < 4; mi++) {
        #pragma unroll
        for (int half = 0; half < 2; half++) {
            const int row = warpM + mi * 16 + g + half * 8;
            const float sqi = sqRs[row];
            const int   ti  = tRs[row];
            float ap = 0.f, an = INF;
            #pragma unroll
            for (int nj = 0; nj < 4; nj++) {
                #pragma unroll
                for (int c = 0; c < 2; c++) {
                    const int col = warpN + nj * 8 + q * 2 + c;
                    float d2 = fmaxf(sqi + sqCs[col] - 2.f * acc[mi][nj][half * 2 + c], 1e-12f);
                    acc[mi][nj][half * 2 + c] = d2;
                    if (ti == tCs[col]) ap = fmaxf(ap, d2);
                    else                an = fminf(an, d2);
                }
            }
            ap = fmaxf(ap, __shfl_xor_sync(0xffffffffu, ap, 1));
            ap = fmaxf(ap, __shfl_xor_sync(0xffffffffu, ap, 2));
            an = fminf(an, __shfl_xor_sync(0xffffffffu, an, 1));
            an = fminf(an, __shfl_xor_sync(0xffffffffu, an, 2));
            if (q == 0) {
                atomicMax(&apS[row], __float_as_uint(ap));
                atomicMin(&anS[row], __float_as_uint(an));
            }
        }
    }
    #pragma unroll
    for (int nj = 0; nj < 4; nj++) {
        #pragma unroll
        for (int c = 0; c < 2; c++) {
            const int col = warpN + nj * 8 + q * 2 + c;
            const int tc = tCs[col];
            float ap = 0.f, an = INF;
            #pragma unroll
            for (int mi = 0; mi < 4; mi++) {
                #pragma unroll
                for (int half = 0; half < 2; half++) {
                    const int row = warpM + mi * 16 + g + half * 8;
                    float d2 = acc[mi][nj][half * 2 + c];
                    if (tRs[row] == tc) ap = fmaxf(ap, d2);
                    else                an = fminf(an, d2);
                }
            }
            ap = fmaxf(ap, __shfl_xor_sync(0xffffffffu, ap, 4));
            ap = fmaxf(ap, __shfl_xor_sync(0xffffffffu, ap, 8));
            ap = fmaxf(ap, __shfl_xor_sync(0xffffffffu, ap, 16));
            an = fminf(an, __shfl_xor_sync(0xffffffffu, an, 4));
            an = fminf(an, __shfl_xor_sync(0xffffffffu, an, 8));
            an = fminf(an, __shfl_xor_sync(0xffffffffu, an, 16));
            if (g == 0) {
                atomicMax(&apSc[col], __float_as_uint(ap));
                atomicMin(&anSc[col], __float_as_uint(an));
            }
        }
    }
    __syncthreads();
    if (tid < 128) {
        atomicMax(&g_ap[rowBase + tid], apS[tid]);
        atomicMin(&g_an[rowBase + tid], anS[tid]);
        atomicMax(&g_ap[colBase + tid], apSc[tid]);
        atomicMin(&g_an[colBase + tid], anSc[tid]);
    }
}

// ---------------- centroid (+ fused cc) / final ----------------
__global__ void __launch_bounds__(256)
centroid_kernel(const float* __restrict__ X, const int* __restrict__ T) {
    __shared__ float sh[8];
    const int i = blockIdx.x;
    const int c = T[i];
    float cnt = (float)g_ccnt[c];
    float a1 = 0.f, a2 = 0.f;
    #pragma unroll
    for (int it = 0; it < 2; it++) {
        int d = threadIdx.x + it * 256;
        float cs = g_csum[c * D_DIM + d];
        float x  = X[(size_t)i * D_DIM + d];
        float tt = g_tot[d];
        float ic = cs / cnt - x;
        float oc = (tt - cs) / ((float)N_ROWS - cnt) - x;
        a1 += ic * ic;
        a2 += oc * oc;
    }
    a1 = blockReduceSum(a1, sh);
    __syncthreads();
    a2 = blockReduceSum(a2, sh);
    if (threadIdx.x == 0) { g_cp[i] = sqrtf(a1); g_cn[i] = sqrtf(a2); }

    // fused cc term: blocks 0..NUM_CL-1 handle class blockIdx.x
    if (i < NUM_CL) {
        const int c2 = i;
        const int cnt2 = g_ccnt[c2];           // uniform across block
        if (cnt2 > 0) {
            float fc = (float)cnt2;
            float a = 0.f;
            #pragma unroll
            for (int it = 0; it < 2; it++) {
                int d = threadIdx.x + it * 256;
                float cs = g_csum[c2 * D_DIM + d];
                float diff = cs / fc - (g_tot[d] - cs) / ((float)N_ROWS - fc);
                a += diff * diff;
            }
            __syncthreads();
            a = blockReduceSum(a, sh);
            if (threadIdx.x == 0) atomicAdd(&g_cc, fc * sqrtf(a));
        }
    }
}

__global__ void final_kernel(float* __restrict__ out) {
    __shared__ float sh[8];
    float s1 = 0.f, s2 = 0.f;
    for (int i = threadIdx.x; i < N_ROWS; i += 256) {
        float ap = sqrtf(__uint_as_float(g_ap[i]));
        float an = sqrtf(__uint_as_float(g_an[i]));
        s1 += fmaxf(ap - an + MARGIN, 0.f);
        s2 += fmaxf(g_cp[i] - g_cn[i] + MARGIN, 0.f);
    }
    s1 = blockReduceSum(s1, sh);
    __syncthreads();
    s2 = blockReduceSum(s2, sh);
    if (threadIdx.x == 0) {
        out[0] = s1 / (float)N_ROWS;
        out[1] = s2 / (float)N_ROWS;
        out[2] = -g_cc / (float)N_ROWS;
    }
}

// ---------------- entry ----------------
extern "C" void kernel_launch(void* const* d_in, const int* in_sizes, int n_in,
                              void* d_out, int out_size) {
    const float* X = (const float*)d_in[0];
    const int*   T = (const int*)d_in[1];
    float* out = (float*)d_out;

    cudaFuncSetAttribute(dist_mma_kernel,
                         cudaFuncAttributeMaxDynamicSharedMemorySize,
                         NSTG * 2 * STG_BYTES);

    prep_kernel<<<N_ROWS, 128>>>(X);                       // 0
    classsum_kernel<<<NUM_CL, 256>>>(X, T);                // 1
    tot_kernel<<<D_DIM, 128>>>();                          // 2

    const int ntiles = NTILE * (NTILE + 1) / 2;            // 528
    dist_mma_kernel<<<ntiles, 256, NSTG * 2 * STG_BYTES>>>(T);   // 3 (profiled)

    centroid_kernel<<<N_ROWS, 256>>>(X, T);                // 4 (+ fused cc)
    final_kernel<<<1, 256>>>(out);                         // 5
}

// round 8
// speedup vs baseline: 6.1288x; 1.0967x over previous
#include <cuda_runtime.h>
#include <cuda_bf16.h>
#include <cstdint>

#define N_ROWS 4096
#define D_DIM  512
#define NUM_CL 512
#define MARGIN 0.3f

// ---------------- device scratch ----------------
__device__ float    g_sq[N_ROWS];
__device__ unsigned g_ap[N_ROWS];          // max intra-class dist^2 (bits)
__device__ unsigned g_an[N_ROWS];          // min inter-class dist^2 (bits)
__device__ float    g_cp[N_ROWS];
__device__ float    g_cn[N_ROWS];
__device__ float    g_csum[NUM_CL * D_DIM];
__device__ int      g_ccnt[NUM_CL];
__device__ float    g_tot[D_DIM];
__device__ float    g_cc;
__device__ __align__(16) __nv_bfloat16 g_xb[N_ROWS * D_DIM];

// ---------------- helpers ----------------
__device__ __forceinline__ uint32_t smem_u32(const void* p) {
    uint32_t a;
    asm("{ .reg .u64 t; cvta.to.shared.u64 t, %1; cvt.u32.u64 %0, t; }" : "=r"(a) : "l"(p));
    return a;
}
__device__ __forceinline__ float blockReduceSum(float v, float* sh) {
    int tid = threadIdx.x;
    #pragma unroll
    for (int o = 16; o; o >>= 1) v += __shfl_down_sync(0xffffffffu, v, o);
    __syncthreads();
    if ((tid & 31) == 0) sh[tid >> 5] = v;
    __syncthreads();
    int nw = (blockDim.x + 31) >> 5;
    if (tid < 32) {
        v = (tid < nw) ? sh[tid] : 0.f;
        #pragma unroll
        for (int o = 16; o; o >>= 1) v += __shfl_down_sync(0xffffffffu, v, o);
    }
    return v;
}

// ---------------- prep: init + fp32->bf16 + squared norms (chain A) -------
__global__ void prep_kernel(const float* __restrict__ X) {
    __shared__ float sh[4];
    int r = blockIdx.x, t = threadIdx.x;   // 128 threads
    const float4 v = *(const float4*)&X[(size_t)r * D_DIM + t * 4];
    __nv_bfloat162 lo = __floats2bfloat162_rn(v.x, v.y);
    __nv_bfloat162 hi = __floats2bfloat162_rn(v.z, v.w);
    *(__nv_bfloat162*)&g_xb[(size_t)r * D_DIM + t * 4]     = lo;
    *(__nv_bfloat162*)&g_xb[(size_t)r * D_DIM + t * 4 + 2] = hi;
    float a = v.x * v.x + v.y * v.y + v.z * v.z + v.w * v.w;
    a = blockReduceSum(a, sh);
    if (t == 0) {
        g_sq[r] = a;
        g_ap[r] = 0u;
        g_an[r] = 0x7f800000u;
    }
}

// one block per class: bitmask membership scan (chain B head)
__global__ void __launch_bounds__(256)
classsum_kernel(const float* __restrict__ X, const int* __restrict__ T) {
    __shared__ unsigned mask[N_ROWS / 32];   // 128 words
    const int c = blockIdx.x, tid = threadIdx.x;

    if (c == 0 && tid == 0) g_cc = 0.f;      // cc accumulator init (chain B owns it)
    if (tid < N_ROWS / 32) mask[tid] = 0u;
    __syncthreads();
    {
        unsigned bits = 0u;
        const int r0 = tid * 16;
        #pragma unroll
        for (int i = 0; i < 16; i++)
            bits |= (T[r0 + i] == c) ? (1u << ((r0 + i) & 31)) : 0u;
        if (bits) atomicOr(&mask[r0 >> 5], bits);
    }
    __syncthreads();

    float a0 = 0.f, a1 = 0.f;
    int cnt = 0;
    #pragma unroll 4
    for (int w = 0; w < N_ROWS / 32; w++) {
        unsigned m = mask[w];
        while (m) {
            int b = __ffs(m) - 1;
            m &= m - 1;
            int r = w * 32 + b;
            cnt++;
            a0 += X[(size_t)r * D_DIM + tid];
            a1 += X[(size_t)r * D_DIM + tid + 256];
        }
    }
    g_csum[c * D_DIM + tid]       = a0;
    g_csum[c * D_DIM + tid + 256] = a1;
    if (tid == 0) g_ccnt[c] = cnt;
}

__global__ void tot_kernel() {   // grid 512, block 128
    __shared__ float sh[4];
    int d = blockIdx.x;
    float s = 0.f;
    for (int c = threadIdx.x; c < NUM_CL; c += 128) s += g_csum[c * D_DIM + d];
    s = blockReduceSum(s, sh);
    if (threadIdx.x == 0) g_tot[d] = s;
}

// ---------------- tensor-core (mma.sync) distance kernel ----------------
#define KC 64
#define STAGES (D_DIM / KC)      // 8
#define NSTG 3
#define STG_BYTES (128 * KC * 2) // 16384 per matrix per stage
#define NTILE 32                 // 4096/128

__device__ __forceinline__ void ldmx4(uint32_t& r0, uint32_t& r1, uint32_t& r2, uint32_t& r3,
                                      uint32_t addr) {
    asm volatile("ldmatrix.sync.aligned.m8n8.x4.shared.b16 {%0,%1,%2,%3}, [%4];"
                 : "=r"(r0), "=r"(r1), "=r"(r2), "=r"(r3) : "r"(addr));
}
__device__ __forceinline__ void mma_bf16(float* c, uint32_t a0, uint32_t a1, uint32_t a2,
                                         uint32_t a3, uint32_t b0, uint32_t b1) {
    asm volatile("mma.sync.aligned.m16n8k16.row.col.f32.bf16.bf16.f32 "
                 "{%0,%1,%2,%3}, {%4,%5,%6,%7}, {%8,%9}, {%0,%1,%2,%3};"
                 : "+f"(c[0]), "+f"(c[1]), "+f"(c[2]), "+f"(c[3])
                 : "r"(a0), "r"(a1), "r"(a2), "r"(a3), "r"(b0), "r"(b1));
}
#define CP16(dst, src) \
    asm volatile("cp.async.cg.shared.global [%0], [%1], 16;" :: "r"(dst), "l"(src))
#define CP_COMMIT() asm volatile("cp.async.commit_group;" ::: "memory")

__global__ void __launch_bounds__(256, 2)
dist_mma_kernel(const int* __restrict__ T) {
    extern __shared__ __align__(1024) unsigned char dsm[];   // NSTG*2*16KB = 96KB
    __shared__ float sqRs[128], sqCs[128];
    __shared__ int   tRs[128], tCs[128];
    __shared__ unsigned apS[128], anS[128], apSc[128], anSc[128];

    // triangular decode: tile t -> (by, bx), bx >= by
    const int t = blockIdx.x;
    int by = (int)((2.f * NTILE + 1.f - sqrtf((2.f * NTILE + 1.f) * (2.f * NTILE + 1.f)
                                              - 8.f * (float)t)) * 0.5f);
    while (by > 0 && (by * NTILE - (by * (by - 1)) / 2) > t) by--;
    while (((by + 1) * NTILE - ((by + 1) * by) / 2) <= t) by++;
    const int bx = by + (t - (by * NTILE - (by * (by - 1)) / 2));

    const int tid = threadIdx.x, wid = tid >> 5, lane = tid & 31;
    const int rowBase = by * 128;
    const int colBase = bx * 128;
    const int warpM = (wid >> 2) * 64;
    const int warpN = (wid & 3) * 32;

    if (tid < 128) {
        sqRs[tid] = g_sq[rowBase + tid];
        sqCs[tid] = g_sq[colBase + tid];
        tRs[tid]  = T[rowBase + tid];
        tCs[tid]  = T[colBase + tid];
        apS[tid] = 0u;  anS[tid] = 0x7f800000u;
        apSc[tid] = 0u; anSc[tid] = 0x7f800000u;
    }

    const uint32_t sbA = smem_u32(dsm);
    const uint32_t sbB = sbA + NSTG * STG_BYTES;
    const char* Xb = (const char*)g_xb;

    uint32_t soL[4];
    size_t gAL[4], gBL[4];
    #pragma unroll
    for (int it = 0; it < 4; it++) {
        int f = tid + it * 256;          // 0..1023
        int r = f >> 3, u = f & 7;
        soL[it] = (uint32_t)(r * 128 + ((u * 16) ^ ((r & 7) << 4)));
        gAL[it] = ((size_t)(rowBase + r) * D_DIM + u * 8) * 2;
        gBL[it] = ((size_t)(colBase + r) * D_DIM + u * 8) * 2;
    }

    #define ISSUE_STAGE(s_) do { \
        const uint32_t bo_ = (uint32_t)(((s_) % NSTG) * STG_BYTES); \
        const size_t ko_ = (size_t)(s_) * (KC * 2); \
        CP16(sbA + bo_ + soL[0], Xb + gAL[0] + ko_); \
        CP16(sbA + bo_ + soL[1], Xb + gAL[1] + ko_); \
        CP16(sbA + bo_ + soL[2], Xb + gAL[2] + ko_); \
        CP16(sbA + bo_ + soL[3], Xb + gAL[3] + ko_); \
        CP16(sbB + bo_ + soL[0], Xb + gBL[0] + ko_); \
        CP16(sbB + bo_ + soL[1], Xb + gBL[1] + ko_); \
        CP16(sbB + bo_ + soL[2], Xb + gBL[2] + ko_); \
        CP16(sbB + bo_ + soL[3], Xb + gBL[3] + ko_); \
        CP_COMMIT(); \
    } while (0)

    const int aRow  = warpM + (lane & 15);
    const int aKH   = (lane >> 4) * 16;
    const uint32_t aXor = ((unsigned)(aRow & 7)) << 4;
    const int nRow  = warpN + (lane & 7) + ((lane >> 4) << 3);
    const int bKH   = ((lane >> 3) & 1) * 16;
    const uint32_t bXor = ((unsigned)(nRow & 7)) << 4;

    float acc[4][4][4];
    #pragma unroll
    for (int i = 0; i < 4; i++)
        #pragma unroll
        for (int j = 0; j < 4; j++)
            #pragma unroll
            for (int c = 0; c < 4; c++) acc[i][j][c] = 0.f;

    ISSUE_STAGE(0);
    ISSUE_STAGE(1);

    for (int s = 0; s < STAGES; s++) {
        if (s < STAGES - 1) asm volatile("cp.async.wait_group 1;" ::: "memory");
        else                asm volatile("cp.async.wait_group 0;" ::: "memory");
        __syncthreads();
        if (s + 2 < STAGES) ISSUE_STAGE(s + 2);

        const uint32_t bufOff = (uint32_t)((s % NSTG) * STG_BYTES);
        #pragma unroll
        for (int ks = 0; ks < 4; ks++) {
            uint32_t b[4][2];
            #pragma unroll
            for (int nb = 0; nb < 2; nb++) {
                uint32_t addr = sbB + bufOff + (uint32_t)((nRow + nb * 16) * 128)
                              + (uint32_t)((ks * 32 + bKH) ^ bXor);
                uint32_t q0, q1, q2, q3;
                ldmx4(q0, q1, q2, q3, addr);
                b[nb * 2][0] = q0; b[nb * 2][1] = q1;
                b[nb * 2 + 1][0] = q2; b[nb * 2 + 1][1] = q3;
            }
            #pragma unroll
            for (int mi = 0; mi < 4; mi++) {
                uint32_t addr = sbA + bufOff + (uint32_t)((aRow + mi * 16) * 128)
                              + (uint32_t)((ks * 32 + aKH) ^ aXor);
                uint32_t a0, a1, a2, a3;
                ldmx4(a0, a1, a2, a3, addr);
                #pragma unroll
                for (int nj = 0; nj < 4; nj++)
                    mma_bf16(acc[mi][nj], a0, a1, a2, a3, b[nj][0], b[nj][1]);
            }
        }
    }

    // ---- epilogue ----
    const int g = lane >> 2, q = lane & 3;
    const float INF = __int_as_float(0x7f800000);

    #pragma unroll
    for (int mi = 0; mi < 4; mi++) {
        #pragma unroll
        for (int half = 0; half < 2; half++) {
            const int row = warpM + mi * 16 + g + half * 8;
            const float sqi = sqRs[row];
            const int   ti  = tRs[row];
            float ap = 0.f, an = INF;
            #pragma unroll
            for (int nj = 0; nj < 4; nj++) {
                #pragma unroll
                for (int c = 0; c < 2; c++) {
                    const int col = warpN + nj * 8 + q * 2 + c;
                    float d2 = fmaxf(sqi + sqCs[col] - 2.f * acc[mi][nj][half * 2 + c], 1e-12f);
                    acc[mi][nj][half * 2 + c] = d2;
                    if (ti == tCs[col]) ap = fmaxf(ap, d2);
                    else                an = fminf(an, d2);
                }
            }
            ap = fmaxf(ap, __shfl_xor_sync(0xffffffffu, ap, 1));
            ap = fmaxf(ap, __shfl_xor_sync(0xffffffffu, ap, 2));
            an = fminf(an, __shfl_xor_sync(0xffffffffu, an, 1));
            an = fminf(an, __shfl_xor_sync(0xffffffffu, an, 2));
            if (q == 0) {
                atomicMax(&apS[row], __float_as_uint(ap));
                atomicMin(&anS[row], __float_as_uint(an));
            }
        }
    }
    #pragma unroll
    for (int nj = 0; nj < 4; nj++) {
        #pragma unroll
        for (int c = 0; c < 2; c++) {
            const int col = warpN + nj * 8 + q * 2 + c;
            const int tc = tCs[col];
            float ap = 0.f, an = INF;
            #pragma unroll
            for (int mi = 0; mi < 4; mi++) {
                #pragma unroll
                for (int half = 0; half < 2; half++) {
                    const int row = warpM + mi * 16 + g + half * 8;
                    float d2 = acc[mi][nj][half * 2 + c];
                    if (tRs[row] == tc) ap = fmaxf(ap, d2);
                    else                an = fminf(an, d2);
                }
            }
            ap = fmaxf(ap, __shfl_xor_sync(0xffffffffu, ap, 4));
            ap = fmaxf(ap, __shfl_xor_sync(0xffffffffu, ap, 8));
            ap = fmaxf(ap, __shfl_xor_sync(0xffffffffu, ap, 16));
            an = fminf(an, __shfl_xor_sync(0xffffffffu, an, 4));
            an = fminf(an, __shfl_xor_sync(0xffffffffu, an, 8));
            an = fminf(an, __shfl_xor_sync(0xffffffffu, an, 16));
            if (g == 0) {
                atomicMax(&apSc[col], __float_as_uint(ap));
                atomicMin(&anSc[col], __float_as_uint(an));
            }
        }
    }
    __syncthreads();
    if (tid < 128) {
        atomicMax(&g_ap[rowBase + tid], apS[tid]);
        atomicMin(&g_an[rowBase + tid], anS[tid]);
        atomicMax(&g_ap[colBase + tid], apSc[tid]);
        atomicMin(&g_an[colBase + tid], anSc[tid]);
    }
}

// ---------------- centroid (+ fused cc) / final ----------------
__global__ void __launch_bounds__(256)
centroid_kernel(const float* __restrict__ X, const int* __restrict__ T) {
    __shared__ float sh[8];
    const int i = blockIdx.x;
    const int c = T[i];
    float cnt = (float)g_ccnt[c];
    float a1 = 0.f, a2 = 0.f;
    #pragma unroll
    for (int it = 0; it < 2; it++) {
        int d = threadIdx.x + it * 256;
        float cs = g_csum[c * D_DIM + d];
        float x  = X[(size_t)i * D_DIM + d];
        float tt = g_tot[d];
        float ic = cs / cnt - x;
        float oc = (tt - cs) / ((float)N_ROWS - cnt) - x;
        a1 += ic * ic;
        a2 += oc * oc;
    }
    a1 = blockReduceSum(a1, sh);
    __syncthreads();
    a2 = blockReduceSum(a2, sh);
    if (threadIdx.x == 0) { g_cp[i] = sqrtf(a1); g_cn[i] = sqrtf(a2); }

    // fused cc term: blocks 0..NUM_CL-1 handle class blockIdx.x
    if (i < NUM_CL) {
        const int c2 = i;
        const int cnt2 = g_ccnt[c2];           // uniform across block
        if (cnt2 > 0) {
            float fc = (float)cnt2;
            float a = 0.f;
            #pragma unroll
            for (int it = 0; it < 2; it++) {
                int d = threadIdx.x + it * 256;
                float cs = g_csum[c2 * D_DIM + d];
                float diff = cs / fc - (g_tot[d] - cs) / ((float)N_ROWS - fc);
                a += diff * diff;
            }
            __syncthreads();
            a = blockReduceSum(a, sh);
            if (threadIdx.x == 0) atomicAdd(&g_cc, fc * sqrtf(a));
        }
    }
}

__global__ void final_kernel(float* __restrict__ out) {
    __shared__ float sh[8];
    float s1 = 0.f, s2 = 0.f;
    for (int i = threadIdx.x; i < N_ROWS; i += 256) {
        float ap = sqrtf(__uint_as_float(g_ap[i]));
        float an = sqrtf(__uint_as_float(g_an[i]));
        s1 += fmaxf(ap - an + MARGIN, 0.f);
        s2 += fmaxf(g_cp[i] - g_cn[i] + MARGIN, 0.f);
    }
    s1 = blockReduceSum(s1, sh);
    __syncthreads();
    s2 = blockReduceSum(s2, sh);
    if (threadIdx.x == 0) {
        out[0] = s1 / (float)N_ROWS;
        out[1] = s2 / (float)N_ROWS;
        out[2] = -g_cc / (float)N_ROWS;
    }
}

// ---------------- entry ----------------
extern "C" void kernel_launch(void* const* d_in, const int* in_sizes, int n_in,
                              void* d_out, int out_size) {
    const float* X = (const float*)d_in[0];
    const int*   T = (const int*)d_in[1];
    float* out = (float*)d_out;

    cudaFuncSetAttribute(dist_mma_kernel,
                         cudaFuncAttributeMaxDynamicSharedMemorySize,
                         NSTG * 2 * STG_BYTES);

    // Side stream + events for the independent centroid chain. Created fresh
    // per call (host-side objects only, no device memory); intentionally not
    // destroyed here: the capture that references them ends after we return.
    cudaStream_t s2;
    cudaStreamCreateWithFlags(&s2, cudaStreamNonBlocking);
    cudaEvent_t eFork, eJoin;
    cudaEventCreateWithFlags(&eFork, cudaEventDisableTiming);
    cudaEventCreateWithFlags(&eJoin, cudaEventDisableTiming);

    // fork
    cudaEventRecord(eFork, 0);
    cudaStreamWaitEvent(s2, eFork, 0);

    // chain A (origin stream): prep -> dist
    prep_kernel<<<N_ROWS, 128>>>(X);

    // chain B (side stream): classsum -> tot -> centroid(+cc)
    classsum_kernel<<<NUM_CL, 256, 0, s2>>>(X, T);
    tot_kernel<<<D_DIM, 128, 0, s2>>>();
    centroid_kernel<<<N_ROWS, 256, 0, s2>>>(X, T);
    cudaEventRecord(eJoin, s2);

    const int ntiles = NTILE * (NTILE + 1) / 2;            // 528
    dist_mma_kernel<<<ntiles, 256, NSTG * 2 * STG_BYTES>>>(T);

    // join, then final reduction
    cudaStreamWaitEvent(0, eJoin, 0);
    final_kernel<<<1, 256>>>(out);
}

// round 9
// speedup vs baseline: 6.5186x; 1.0636x over previous
#include <cuda_runtime.h>
#include <cuda_bf16.h>
#include <cstdint>

#define N_ROWS 4096
#define D_DIM  512
#define NUM_CL 512
#define MARGIN 0.3f

// ---------------- device scratch ----------------
__device__ float    g_sq[N_ROWS];
__device__ unsigned g_ap[N_ROWS];          // max intra-class dist^2 (bits)
__device__ unsigned g_an[N_ROWS];          // min inter-class dist^2 (bits)
__device__ float    g_cp[N_ROWS];
__device__ float    g_cn[N_ROWS];
__device__ float    g_csum[NUM_CL * D_DIM];
__device__ int      g_ccnt[NUM_CL];
__device__ float    g_tot[D_DIM];
__device__ float    g_cc;
__device__ __align__(16) __nv_bfloat16 g_xb[N_ROWS * D_DIM];

// ---------------- helpers ----------------
__device__ __forceinline__ uint32_t smem_u32(const void* p) {
    uint32_t a;
    asm("{ .reg .u64 t; cvta.to.shared.u64 t, %1; cvt.u32.u64 %0, t; }" : "=r"(a) : "l"(p));
    return a;
}
__device__ __forceinline__ float blockReduceSum(float v, float* sh) {
    int tid = threadIdx.x;
    #pragma unroll
    for (int o = 16; o; o >>= 1) v += __shfl_down_sync(0xffffffffu, v, o);
    __syncthreads();
    if ((tid & 31) == 0) sh[tid >> 5] = v;
    __syncthreads();
    int nw = (blockDim.x + 31) >> 5;
    if (tid < 32) {
        v = (tid < nw) ? sh[tid] : 0.f;
        #pragma unroll
        for (int o = 16; o; o >>= 1) v += __shfl_down_sync(0xffffffffu, v, o);
    }
    return v;
}
__device__ __forceinline__ float warpReduceSum(float v) {
    #pragma unroll
    for (int o = 16; o; o >>= 1) v += __shfl_down_sync(0xffffffffu, v, o);
    return v;
}

// ---------------- prep: init + fp32->bf16 + squared norms (chain A) -------
__global__ void prep_kernel(const float* __restrict__ X) {
    __shared__ float sh[4];
    int r = blockIdx.x, t = threadIdx.x;   // 128 threads
    const float4 v = *(const float4*)&X[(size_t)r * D_DIM + t * 4];
    __nv_bfloat162 lo = __floats2bfloat162_rn(v.x, v.y);
    __nv_bfloat162 hi = __floats2bfloat162_rn(v.z, v.w);
    *(__nv_bfloat162*)&g_xb[(size_t)r * D_DIM + t * 4]     = lo;
    *(__nv_bfloat162*)&g_xb[(size_t)r * D_DIM + t * 4 + 2] = hi;
    float a = v.x * v.x + v.y * v.y + v.z * v.z + v.w * v.w;
    a = blockReduceSum(a, sh);
    if (t == 0) {
        g_sq[r] = a;
        g_ap[r] = 0u;
        g_an[r] = 0x7f800000u;
    }
}

// one block per class: bitmask membership scan (chain B head)
__global__ void __launch_bounds__(256)
classsum_kernel(const float* __restrict__ X, const int* __restrict__ T) {
    __shared__ unsigned mask[N_ROWS / 32];   // 128 words
    const int c = blockIdx.x, tid = threadIdx.x;

    if (c == 0 && tid == 0) g_cc = 0.f;      // cc accumulator init (chain B owns it)
    if (tid < N_ROWS / 32) mask[tid] = 0u;
    __syncthreads();
    {
        unsigned bits = 0u;
        const int r0 = tid * 16;
        #pragma unroll
        for (int i = 0; i < 16; i++)
            bits |= (T[r0 + i] == c) ? (1u << ((r0 + i) & 31)) : 0u;
        if (bits) atomicOr(&mask[r0 >> 5], bits);
    }
    __syncthreads();

    float a0 = 0.f, a1 = 0.f;
    int cnt = 0;
    #pragma unroll 4
    for (int w = 0; w < N_ROWS / 32; w++) {
        unsigned m = mask[w];
        while (m) {
            int b = __ffs(m) - 1;
            m &= m - 1;
            int r = w * 32 + b;
            cnt++;
            a0 += X[(size_t)r * D_DIM + tid];
            a1 += X[(size_t)r * D_DIM + tid + 256];
        }
    }
    g_csum[c * D_DIM + tid]       = a0;
    g_csum[c * D_DIM + tid + 256] = a1;
    if (tid == 0) g_ccnt[c] = cnt;
}

__global__ void tot_kernel() {   // grid 512, block 128
    __shared__ float sh[4];
    int d = blockIdx.x;
    float s = 0.f;
    for (int c = threadIdx.x; c < NUM_CL; c += 128) s += g_csum[c * D_DIM + d];
    s = blockReduceSum(s, sh);
    if (threadIdx.x == 0) g_tot[d] = s;
}

// ---------------- tensor-core (mma.sync) distance kernel ----------------
#define KC 64
#define STAGES (D_DIM / KC)      // 8
#define NSTG 3
#define STG_BYTES (128 * KC * 2) // 16384 per matrix per stage
#define NTILE 32                 // 4096/128

__device__ __forceinline__ void ldmx4(uint32_t& r0, uint32_t& r1, uint32_t& r2, uint32_t& r3,
                                      uint32_t addr) {
    asm volatile("ldmatrix.sync.aligned.m8n8.x4.shared.b16 {%0,%1,%2,%3}, [%4];"
                 : "=r"(r0), "=r"(r1), "=r"(r2), "=r"(r3) : "r"(addr));
}
__device__ __forceinline__ void mma_bf16(float* c, uint32_t a0, uint32_t a1, uint32_t a2,
                                         uint32_t a3, uint32_t b0, uint32_t b1) {
    asm volatile("mma.sync.aligned.m16n8k16.row.col.f32.bf16.bf16.f32 "
                 "{%0,%1,%2,%3}, {%4,%5,%6,%7}, {%8,%9}, {%0,%1,%2,%3};"
                 : "+f"(c[0]), "+f"(c[1]), "+f"(c[2]), "+f"(c[3])
                 : "r"(a0), "r"(a1), "r"(a2), "r"(a3), "r"(b0), "r"(b1));
}
#define CP16(dst, src) \
    asm volatile("cp.async.cg.shared.global [%0], [%1], 16;" :: "r"(dst), "l"(src))
#define CP_COMMIT() asm volatile("cp.async.commit_group;" ::: "memory")

__global__ void __launch_bounds__(256, 2)
dist_mma_kernel(const int* __restrict__ T) {
    extern __shared__ __align__(1024) unsigned char dsm[];   // NSTG*2*16KB = 96KB
    __shared__ float sqRs[128], sqCs[128];
    __shared__ int   tRs[128], tCs[128];
    __shared__ unsigned apS[128], anS[128], apSc[128], anSc[128];

    // triangular decode: tile t -> (by, bx), bx >= by
    const int t = blockIdx.x;
    int by = (int)((2.f * NTILE + 1.f - sqrtf((2.f * NTILE + 1.f) * (2.f * NTILE + 1.f)
                                              - 8.f * (float)t)) * 0.5f);
    while (by > 0 && (by * NTILE - (by * (by - 1)) / 2) > t) by--;
    while (((by + 1) * NTILE - ((by + 1) * by) / 2) <= t) by++;
    const int bx = by + (t - (by * NTILE - (by * (by - 1)) / 2));

    const int tid = threadIdx.x, wid = tid >> 5, lane = tid & 31;
    const int rowBase = by * 128;
    const int colBase = bx * 128;
    const int warpM = (wid >> 2) * 64;
    const int warpN = (wid & 3) * 32;

    if (tid < 128) {
        sqRs[tid] = g_sq[rowBase + tid];
        sqCs[tid] = g_sq[colBase + tid];
        tRs[tid]  = T[rowBase + tid];
        tCs[tid]  = T[colBase + tid];
        apS[tid] = 0u;  anS[tid] = 0x7f800000u;
        apSc[tid] = 0u; anSc[tid] = 0x7f800000u;
    }

    const uint32_t sbA = smem_u32(dsm);
    const uint32_t sbB = sbA + NSTG * STG_BYTES;
    const char* Xb = (const char*)g_xb;

    uint32_t soL[4];
    size_t gAL[4], gBL[4];
    #pragma unroll
    for (int it = 0; it < 4; it++) {
        int f = tid + it * 256;          // 0..1023
        int r = f >> 3, u = f & 7;
        soL[it] = (uint32_t)(r * 128 + ((u * 16) ^ ((r & 7) << 4)));
        gAL[it] = ((size_t)(rowBase + r) * D_DIM + u * 8) * 2;
        gBL[it] = ((size_t)(colBase + r) * D_DIM + u * 8) * 2;
    }

    #define ISSUE_STAGE(s_) do { \
        const uint32_t bo_ = (uint32_t)(((s_) % NSTG) * STG_BYTES); \
        const size_t ko_ = (size_t)(s_) * (KC * 2); \
        CP16(sbA + bo_ + soL[0], Xb + gAL[0] + ko_); \
        CP16(sbA + bo_ + soL[1], Xb + gAL[1] + ko_); \
        CP16(sbA + bo_ + soL[2], Xb + gAL[2] + ko_); \
        CP16(sbA + bo_ + soL[3], Xb + gAL[3] + ko_); \
        CP16(sbB + bo_ + soL[0], Xb + gBL[0] + ko_); \
        CP16(sbB + bo_ + soL[1], Xb + gBL[1] + ko_); \
        CP16(sbB + bo_ + soL[2], Xb + gBL[2] + ko_); \
        CP16(sbB + bo_ + soL[3], Xb + gBL[3] + ko_); \
        CP_COMMIT(); \
    } while (0)

    const int aRow  = warpM + (lane & 15);
    const int aKH   = (lane >> 4) * 16;
    const uint32_t aXor = ((unsigned)(aRow & 7)) << 4;
    const int nRow  = warpN + (lane & 7) + ((lane >> 4) << 3);
    const int bKH   = ((lane >> 3) & 1) * 16;
    const uint32_t bXor = ((unsigned)(nRow & 7)) << 4;

    float acc[4][4][4];
    #pragma unroll
    for (int i = 0; i < 4; i++)
        #pragma unroll
        for (int j = 0; j < 4; j++)
            #pragma unroll
            for (int c = 0; c < 4; c++) acc[i][j][c] = 0.f;

    ISSUE_STAGE(0);
    ISSUE_STAGE(1);

    for (int s = 0; s < STAGES; s++) {
        if (s < STAGES - 1) asm volatile("cp.async.wait_group 1;" ::: "memory");
        else                asm volatile("cp.async.wait_group 0;" ::: "memory");
        __syncthreads();
        if (s + 2 < STAGES) ISSUE_STAGE(s + 2);

        const uint32_t bufOff = (uint32_t)((s % NSTG) * STG_BYTES);
        #pragma unroll
        for (int ks = 0; ks < 4; ks++) {
            uint32_t b[4][2];
            #pragma unroll
            for (int nb = 0; nb < 2; nb++) {
                uint32_t addr = sbB + bufOff + (uint32_t)((nRow + nb * 16) * 128)
                              + (uint32_t)((ks * 32 + bKH) ^ bXor);
                uint32_t q0, q1, q2, q3;
                ldmx4(q0, q1, q2, q3, addr);
                b[nb * 2][0] = q0; b[nb * 2][1] = q1;
                b[nb * 2 + 1][0] = q2; b[nb * 2 + 1][1] = q3;
            }
            #pragma unroll
            for (int mi = 0; mi < 4; mi++) {
                uint32_t addr = sbA + bufOff + (uint32_t)((aRow + mi * 16) * 128)
                              + (uint32_t)((ks * 32 + aKH) ^ aXor);
                uint32_t a0, a1, a2, a3;
                ldmx4(a0, a1, a2, a3, addr);
                #pragma unroll
                for (int nj = 0; nj < 4; nj++)
                    mma_bf16(acc[mi][nj], a0, a1, a2, a3, b[nj][0], b[nj][1]);
            }
        }
    }

    // ---- epilogue ----
    const int g = lane >> 2, q = lane & 3;
    const float INF = __int_as_float(0x7f800000);

    #pragma unroll
    for (int mi = 0; mi < 4; mi++) {
        #pragma unroll
        for (int half = 0; half < 2; half++) {
            const int row = warpM + mi * 16 + g + half * 8;
            const float sqi = sqRs[row];
            const int   ti  = tRs[row];
            float ap = 0.f, an = INF;
            #pragma unroll
            for (int nj = 0; nj < 4; nj++) {
                #pragma unroll
                for (int c = 0; c < 2; c++) {
                    const int col = warpN + nj * 8 + q * 2 + c;
                    float d2 = fmaxf(sqi + sqCs[col] - 2.f * acc[mi][nj][half * 2 + c], 1e-12f);
                    acc[mi][nj][half * 2 + c] = d2;
                    if (ti == tCs[col]) ap = fmaxf(ap, d2);
                    else                an = fminf(an, d2);
                }
            }
            ap = fmaxf(ap, __shfl_xor_sync(0xffffffffu, ap, 1));
            ap = fmaxf(ap, __shfl_xor_sync(0xffffffffu, ap, 2));
            an = fminf(an, __shfl_xor_sync(0xffffffffu, an, 1));
            an = fminf(an, __shfl_xor_sync(0xffffffffu, an, 2));
            if (q == 0) {
                atomicMax(&apS[row], __float_as_uint(ap));
                atomicMin(&anS[row], __float_as_uint(an));
            }
        }
    }
    #pragma unroll
    for (int nj = 0; nj < 4; nj++) {
        #pragma unroll
        for (int c = 0; c < 2; c++) {
            const int col = warpN + nj * 8 + q * 2 + c;
            const int tc = tCs[col];
            float ap = 0.f, an = INF;
            #pragma unroll
            for (int mi = 0; mi < 4; mi++) {
                #pragma unroll
                for (int half = 0; half < 2; half++) {
                    const int row = warpM + mi * 16 + g + half * 8;
                    float d2 = acc[mi][nj][half * 2 + c];
                    if (tRs[row] == tc) ap = fmaxf(ap, d2);
                    else                an = fminf(an, d2);
                }
            }
            ap = fmaxf(ap, __shfl_xor_sync(0xffffffffu, ap, 4));
            ap = fmaxf(ap, __shfl_xor_sync(0xffffffffu, ap, 8));
            ap = fmaxf(ap, __shfl_xor_sync(0xffffffffu, ap, 16));
            an = fminf(an, __shfl_xor_sync(0xffffffffu, an, 4));
            an = fminf(an, __shfl_xor_sync(0xffffffffu, an, 8));
            an = fminf(an, __shfl_xor_sync(0xffffffffu, an, 16));
            if (g == 0) {
                atomicMax(&apSc[col], __float_as_uint(ap));
                atomicMin(&anSc[col], __float_as_uint(an));
            }
        }
    }
    __syncthreads();
    if (tid < 128) {
        atomicMax(&g_ap[rowBase + tid], apS[tid]);
        atomicMin(&g_an[rowBase + tid], anS[tid]);
        atomicMax(&g_ap[colBase + tid], apSc[tid]);
        atomicMin(&g_an[colBase + tid], anSc[tid]);
    }
}

// ---------------- centroid (+ fused cc): warp per row ----------------
__global__ void __launch_bounds__(256)
centroid_kernel(const float* __restrict__ X, const int* __restrict__ T) {
    const int warp = threadIdx.x >> 5, lane = threadIdx.x & 31;
    const int i = blockIdx.x * 8 + warp;           // row; grid = 512
    const int c = T[i];
    const float cnt  = (float)g_ccnt[c];
    const float inv1 = 1.f / cnt;
    const float inv2 = 1.f / ((float)N_ROWS - cnt);

    float a1 = 0.f, a2 = 0.f;
    #pragma unroll
    for (int it = 0; it < 4; it++) {
        const int d = (lane + it * 32) * 4;
        const float4 cs = *(const float4*)&g_csum[c * D_DIM + d];
        const float4 x  = *(const float4*)&X[(size_t)i * D_DIM + d];
        const float4 tt = *(const float4*)&g_tot[d];
        float icx = cs.x * inv1 - x.x, icy = cs.y * inv1 - x.y;
        float icz = cs.z * inv1 - x.z, icw = cs.w * inv1 - x.w;
        a1 += icx * icx + icy * icy + icz * icz + icw * icw;
        float ocx = (tt.x - cs.x) * inv2 - x.x, ocy = (tt.y - cs.y) * inv2 - x.y;
        float ocz = (tt.z - cs.z) * inv2 - x.z, ocw = (tt.w - cs.w) * inv2 - x.w;
        a2 += ocx * ocx + ocy * ocy + ocz * ocz + ocw * ocw;
    }
    a1 = warpReduceSum(a1);
    a2 = warpReduceSum(a2);
    if (lane == 0) { g_cp[i] = sqrtf(a1); g_cn[i] = sqrtf(a2); }

    // fused cc: warps owning rows 0..NUM_CL-1 also handle class = row index
    if (i < NUM_CL) {
        const int cnt2 = g_ccnt[i];
        if (cnt2 > 0) {
            const float fc = (float)cnt2;
            const float j1 = 1.f / fc;
            const float j2 = 1.f / ((float)N_ROWS - fc);
            float a = 0.f;
            #pragma unroll
            for (int it = 0; it < 4; it++) {
                const int d = (lane + it * 32) * 4;
                const float4 cs = *(const float4*)&g_csum[i * D_DIM + d];
                const float4 tt = *(const float4*)&g_tot[d];
                float dx = cs.x * j1 - (tt.x - cs.x) * j2;
                float dy = cs.y * j1 - (tt.y - cs.y) * j2;
                float dz = cs.z * j1 - (tt.z - cs.z) * j2;
                float dw = cs.w * j1 - (tt.w - cs.w) * j2;
                a += dx * dx + dy * dy + dz * dz + dw * dw;
            }
            a = warpReduceSum(a);
            if (lane == 0) atomicAdd(&g_cc, fc * sqrtf(a));
        }
    }
}

__global__ void final_kernel(float* __restrict__ out) {
    __shared__ float sh[8];
    float s1 = 0.f, s2 = 0.f;
    for (int i = threadIdx.x; i < N_ROWS; i += 256) {
        float ap = sqrtf(__uint_as_float(g_ap[i]));
        float an = sqrtf(__uint_as_float(g_an[i]));
        s1 += fmaxf(ap - an + MARGIN, 0.f);
        s2 += fmaxf(g_cp[i] - g_cn[i] + MARGIN, 0.f);
    }
    s1 = blockReduceSum(s1, sh);
    __syncthreads();
    s2 = blockReduceSum(s2, sh);
    if (threadIdx.x == 0) {
        out[0] = s1 / (float)N_ROWS;
        out[1] = s2 / (float)N_ROWS;
        out[2] = -g_cc / (float)N_ROWS;
    }
}

// ---------------- entry ----------------
extern "C" void kernel_launch(void* const* d_in, const int* in_sizes, int n_in,
                              void* d_out, int out_size) {
    const float* X = (const float*)d_in[0];
    const int*   T = (const int*)d_in[1];
    float* out = (float*)d_out;

    cudaFuncSetAttribute(dist_mma_kernel,
                         cudaFuncAttributeMaxDynamicSharedMemorySize,
                         NSTG * 2 * STG_BYTES);

    cudaStream_t s2;
    cudaStreamCreateWithFlags(&s2, cudaStreamNonBlocking);
    cudaEvent_t eFork, eJoin;
    cudaEventCreateWithFlags(&eFork, cudaEventDisableTiming);
    cudaEventCreateWithFlags(&eJoin, cudaEventDisableTiming);

    // fork
    cudaEventRecord(eFork, 0);
    cudaStreamWaitEvent(s2, eFork, 0);

    // chain A (origin stream): prep -> dist
    prep_kernel<<<N_ROWS, 128>>>(X);

    // chain B (side stream): classsum -> tot -> centroid(+cc)
    classsum_kernel<<<NUM_CL, 256, 0, s2>>>(X, T);
    tot_kernel<<<D_DIM, 128, 0, s2>>>();
    centroid_kernel<<<N_ROWS / 8, 256, 0, s2>>>(X, T);
    cudaEventRecord(eJoin, s2);

    const int ntiles = NTILE * (NTILE + 1) / 2;            // 528
    dist_mma_kernel<<<ntiles, 256, NSTG * 2 * STG_BYTES>>>(T);

    // join, then final reduction
    cudaStreamWaitEvent(0, eJoin, 0);
    final_kernel<<<1, 256>>>(out);
}

// round 10
// speedup vs baseline: 6.7166x; 1.0304x over previous
#include <cuda_runtime.h>
#include <cuda_bf16.h>
#include <cstdint>

#define N_ROWS 4096
#define D_DIM  512
#define NUM_CL 512
#define MARGIN 0.3f

// ---------------- device scratch ----------------
__device__ float    g_sq[N_ROWS];
__device__ unsigned g_ap[N_ROWS];          // max intra-class dist^2 (bits)
__device__ unsigned g_an[N_ROWS];          // min inter-class dist^2 (bits)
__device__ float    g_cp[N_ROWS];
__device__ float    g_cn[N_ROWS];
__device__ float    g_csum[NUM_CL * D_DIM];
__device__ int      g_ccnt[NUM_CL];
__device__ float    g_tot[D_DIM];
__device__ float    g_cc;
__device__ __align__(16) __nv_bfloat16 g_xb[N_ROWS * D_DIM];

// ---------------- helpers ----------------
__device__ __forceinline__ uint32_t smem_u32(const void* p) {
    uint32_t a;
    asm("{ .reg .u64 t; cvta.to.shared.u64 t, %1; cvt.u32.u64 %0, t; }" : "=r"(a) : "l"(p));
    return a;
}
__device__ __forceinline__ float blockReduceSum(float v, float* sh) {
    int tid = threadIdx.x;
    #pragma unroll
    for (int o = 16; o; o >>= 1) v += __shfl_down_sync(0xffffffffu, v, o);
    __syncthreads();
    if ((tid & 31) == 0) sh[tid >> 5] = v;
    __syncthreads();
    int nw = (blockDim.x + 31) >> 5;
    if (tid < 32) {
        v = (tid < nw) ? sh[tid] : 0.f;
        #pragma unroll
        for (int o = 16; o; o >>= 1) v += __shfl_down_sync(0xffffffffu, v, o);
    }
    return v;
}
__device__ __forceinline__ float warpReduceSum(float v) {
    #pragma unroll
    for (int o = 16; o; o >>= 1) v += __shfl_down_sync(0xffffffffu, v, o);
    return v;
}

// ---------------- prep: init + fp32->bf16 + squared norms (chain A) -------
__global__ void prep_kernel(const float* __restrict__ X) {
    __shared__ float sh[4];
    int r = blockIdx.x, t = threadIdx.x;   // 128 threads
    const float4 v = *(const float4*)&X[(size_t)r * D_DIM + t * 4];
    __nv_bfloat162 lo = __floats2bfloat162_rn(v.x, v.y);
    __nv_bfloat162 hi = __floats2bfloat162_rn(v.z, v.w);
    *(__nv_bfloat162*)&g_xb[(size_t)r * D_DIM + t * 4]     = lo;
    *(__nv_bfloat162*)&g_xb[(size_t)r * D_DIM + t * 4 + 2] = hi;
    float a = v.x * v.x + v.y * v.y + v.z * v.z + v.w * v.w;
    a = blockReduceSum(a, sh);
    if (t == 0) {
        g_sq[r] = a;
        g_ap[r] = 0u;
        g_an[r] = 0x7f800000u;
    }
}

// one block per class: bitmask membership scan (chain B head)
__global__ void __launch_bounds__(256)
classsum_kernel(const float* __restrict__ X, const int* __restrict__ T) {
    __shared__ unsigned mask[N_ROWS / 32];   // 128 words
    const int c = blockIdx.x, tid = threadIdx.x;

    if (c == 0 && tid == 0) g_cc = 0.f;      // cc accumulator init (chain B owns it)
    if (tid < N_ROWS / 32) mask[tid] = 0u;
    __syncthreads();
    {
        unsigned bits = 0u;
        const int r0 = tid * 16;
        #pragma unroll
        for (int i = 0; i < 16; i++)
            bits |= (T[r0 + i] == c) ? (1u << ((r0 + i) & 31)) : 0u;
        if (bits) atomicOr(&mask[r0 >> 5], bits);
    }
    __syncthreads();

    float a0 = 0.f, a1 = 0.f;
    int cnt = 0;
    #pragma unroll 4
    for (int w = 0; w < N_ROWS / 32; w++) {
        unsigned m = mask[w];
        while (m) {
            int b = __ffs(m) - 1;
            m &= m - 1;
            int r = w * 32 + b;
            cnt++;
            a0 += X[(size_t)r * D_DIM + tid];
            a1 += X[(size_t)r * D_DIM + tid + 256];
        }
    }
    g_csum[c * D_DIM + tid]       = a0;
    g_csum[c * D_DIM + tid + 256] = a1;
    if (tid == 0) g_ccnt[c] = cnt;
}

__global__ void tot_kernel() {   // grid 512, block 128
    __shared__ float sh[4];
    int d = blockIdx.x;
    float s = 0.f;
    for (int c = threadIdx.x; c < NUM_CL; c += 128) s += g_csum[c * D_DIM + d];
    s = blockReduceSum(s, sh);
    if (threadIdx.x == 0) g_tot[d] = s;
}

// ---------------- tensor-core (mma.sync) distance kernel ----------------
#define KC 64
#define STAGES (D_DIM / KC)      // 8
#define NSTG 3
#define STG_BYTES (128 * KC * 2) // 16384 per matrix per stage
#define NTILE 32                 // 4096/128

__device__ __forceinline__ void ldmx4(uint32_t& r0, uint32_t& r1, uint32_t& r2, uint32_t& r3,
                                      uint32_t addr) {
    asm volatile("ldmatrix.sync.aligned.m8n8.x4.shared.b16 {%0,%1,%2,%3}, [%4];"
                 : "=r"(r0), "=r"(r1), "=r"(r2), "=r"(r3) : "r"(addr));
}
__device__ __forceinline__ void mma_bf16(float* c, uint32_t a0, uint32_t a1, uint32_t a2,
                                         uint32_t a3, uint32_t b0, uint32_t b1) {
    asm volatile("mma.sync.aligned.m16n8k16.row.col.f32.bf16.bf16.f32 "
                 "{%0,%1,%2,%3}, {%4,%5,%6,%7}, {%8,%9}, {%0,%1,%2,%3};"
                 : "+f"(c[0]), "+f"(c[1]), "+f"(c[2]), "+f"(c[3])
                 : "r"(a0), "r"(a1), "r"(a2), "r"(a3), "r"(b0), "r"(b1));
}
#define CP16(dst, src) \
    asm volatile("cp.async.cg.shared.global [%0], [%1], 16;" :: "r"(dst), "l"(src))
#define CP_COMMIT() asm volatile("cp.async.commit_group;" ::: "memory")

__global__ void __launch_bounds__(256, 2)
dist_mma_kernel(const int* __restrict__ T) {
    extern __shared__ __align__(1024) unsigned char dsm[];   // NSTG*2*16KB = 96KB
    __shared__ float sqRs[128], sqCs[128];
    __shared__ int   tRs[128], tCs[128];
    __shared__ unsigned apS[128], anS[128], apSc[128], anSc[128];

    // ---- pre-PDL-wait setup: no global reads of prep outputs here ----
    const int t = blockIdx.x;
    int by = (int)((2.f * NTILE + 1.f - sqrtf((2.f * NTILE + 1.f) * (2.f * NTILE + 1.f)
                                              - 8.f * (float)t)) * 0.5f);
    while (by > 0 && (by * NTILE - (by * (by - 1)) / 2) > t) by--;
    while (((by + 1) * NTILE - ((by + 1) * by) / 2) <= t) by++;
    const int bx = by + (t - (by * NTILE - (by * (by - 1)) / 2));

    const int tid = threadIdx.x, wid = tid >> 5, lane = tid & 31;
    const int rowBase = by * 128;
    const int colBase = bx * 128;
    const int warpM = (wid >> 2) * 64;
    const int warpN = (wid & 3) * 32;

    if (tid < 128) {
        apS[tid] = 0u;  anS[tid] = 0x7f800000u;
        apSc[tid] = 0u; anSc[tid] = 0x7f800000u;
    }

    const uint32_t sbA = smem_u32(dsm);
    const uint32_t sbB = sbA + NSTG * STG_BYTES;
    const char* Xb = (const char*)g_xb;

    uint32_t soL[4];
    size_t gAL[4], gBL[4];
    #pragma unroll
    for (int it = 0; it < 4; it++) {
        int f = tid + it * 256;          // 0..1023
        int r = f >> 3, u = f & 7;
        soL[it] = (uint32_t)(r * 128 + ((u * 16) ^ ((r & 7) << 4)));
        gAL[it] = ((size_t)(rowBase + r) * D_DIM + u * 8) * 2;
        gBL[it] = ((size_t)(colBase + r) * D_DIM + u * 8) * 2;
    }

    const int aRow  = warpM + (lane & 15);
    const int aKH   = (lane >> 4) * 16;
    const uint32_t aXor = ((unsigned)(aRow & 7)) << 4;
    const int nRow  = warpN + (lane & 7) + ((lane >> 4) << 3);
    const int bKH   = ((lane >> 3) & 1) * 16;
    const uint32_t bXor = ((unsigned)(nRow & 7)) << 4;

    float acc[4][4][4];
    #pragma unroll
    for (int i = 0; i < 4; i++)
        #pragma unroll
        for (int j = 0; j < 4; j++)
            #pragma unroll
            for (int c = 0; c < 4; c++) acc[i][j][c] = 0.f;

    // ---- PDL: wait for prep's writes to be visible ----
    asm volatile("griddepcontrol.wait;" ::: "memory");

    if (tid < 128) {
        sqRs[tid] = g_sq[rowBase + tid];
        sqCs[tid] = g_sq[colBase + tid];
        tRs[tid]  = T[rowBase + tid];
        tCs[tid]  = T[colBase + tid];
    }

    #define ISSUE_STAGE(s_) do { \
        const uint32_t bo_ = (uint32_t)(((s_) % NSTG) * STG_BYTES); \
        const size_t ko_ = (size_t)(s_) * (KC * 2); \
        CP16(sbA + bo_ + soL[0], Xb + gAL[0] + ko_); \
        CP16(sbA + bo_ + soL[1], Xb + gAL[1] + ko_); \
        CP16(sbA + bo_ + soL[2], Xb + gAL[2] + ko_); \
        CP16(sbA + bo_ + soL[3], Xb + gAL[3] + ko_); \
        CP16(sbB + bo_ + soL[0], Xb + gBL[0] + ko_); \
        CP16(sbB + bo_ + soL[1], Xb + gBL[1] + ko_); \
        CP16(sbB + bo_ + soL[2], Xb + gBL[2] + ko_); \
        CP16(sbB + bo_ + soL[3], Xb + gBL[3] + ko_); \
        CP_COMMIT(); \
    } while (0)

    ISSUE_STAGE(0);
    ISSUE_STAGE(1);

    #pragma unroll
    for (int s = 0; s < STAGES; s++) {
        if (s < STAGES - 1) asm volatile("cp.async.wait_group 1;" ::: "memory");
        else                asm volatile("cp.async.wait_group 0;" ::: "memory");
        __syncthreads();
        if (s + 2 < STAGES) ISSUE_STAGE(s + 2);

        const uint32_t bufOff = (uint32_t)((s % NSTG) * STG_BYTES);
        #pragma unroll
        for (int ks = 0; ks < 4; ks++) {
            uint32_t b[4][2];
            #pragma unroll
            for (int nb = 0; nb < 2; nb++) {
                uint32_t addr = sbB + bufOff + (uint32_t)((nRow + nb * 16) * 128)
                              + (uint32_t)((ks * 32 + bKH) ^ bXor);
                uint32_t q0, q1, q2, q3;
                ldmx4(q0, q1, q2, q3, addr);
                b[nb * 2][0] = q0; b[nb * 2][1] = q1;
                b[nb * 2 + 1][0] = q2; b[nb * 2 + 1][1] = q3;
            }
            #pragma unroll
            for (int mi = 0; mi < 4; mi++) {
                uint32_t addr = sbA + bufOff + (uint32_t)((aRow + mi * 16) * 128)
                              + (uint32_t)((ks * 32 + aKH) ^ aXor);
                uint32_t a0, a1, a2, a3;
                ldmx4(a0, a1, a2, a3, addr);
                #pragma unroll
                for (int nj = 0; nj < 4; nj++)
                    mma_bf16(acc[mi][nj], a0, a1, a2, a3, b[nj][0], b[nj][1]);
            }
        }
    }

    // ---- epilogue ----
    const int g = lane >> 2, q = lane & 3;
    const float INF = __int_as_float(0x7f800000);

    #pragma unroll
    for (int mi = 0; mi < 4; mi++) {
        #pragma unroll
        for (int half = 0; half < 2; half++) {
            const int row = warpM + mi * 16 + g + half * 8;
            const float sqi = sqRs[row];
            const int   ti  = tRs[row];
            float ap = 0.f, an = INF;
            #pragma unroll
            for (int nj = 0; nj < 4; nj++) {
                #pragma unroll
                for (int c = 0; c < 2; c++) {
                    const int col = warpN + nj * 8 + q * 2 + c;
                    float d2 = fmaxf(sqi + sqCs[col] - 2.f * acc[mi][nj][half * 2 + c], 1e-12f);
                    acc[mi][nj][half * 2 + c] = d2;
                    if (ti == tCs[col]) ap = fmaxf(ap, d2);
                    else                an = fminf(an, d2);
                }
            }
            ap = fmaxf(ap, __shfl_xor_sync(0xffffffffu, ap, 1));
            ap = fmaxf(ap, __shfl_xor_sync(0xffffffffu, ap, 2));
            an = fminf(an, __shfl_xor_sync(0xffffffffu, an, 1));
            an = fminf(an, __shfl_xor_sync(0xffffffffu, an, 2));
            if (q == 0) {
                atomicMax(&apS[row], __float_as_uint(ap));
                atomicMin(&anS[row], __float_as_uint(an));
            }
        }
    }
    if (bx != by) {   // diagonal tiles: column pass duplicates row pass
        #pragma unroll
        for (int nj = 0; nj < 4; nj++) {
            #pragma unroll
            for (int c = 0; c < 2; c++) {
                const int col = warpN + nj * 8 + q * 2 + c;
                const int tc = tCs[col];
                float ap = 0.f, an = INF;
                #pragma unroll
                for (int mi = 0; mi < 4; mi++) {
                    #pragma unroll
                    for (int half = 0; half < 2; half++) {
                        const int row = warpM + mi * 16 + g + half * 8;
                        float d2 = acc[mi][nj][half * 2 + c];
                        if (tRs[row] == tc) ap = fmaxf(ap, d2);
                        else                an = fminf(an, d2);
                    }
                }
                ap = fmaxf(ap, __shfl_xor_sync(0xffffffffu, ap, 4));
                ap = fmaxf(ap, __shfl_xor_sync(0xffffffffu, ap, 8));
                ap = fmaxf(ap, __shfl_xor_sync(0xffffffffu, ap, 16));
                an = fminf(an, __shfl_xor_sync(0xffffffffu, an, 4));
                an = fminf(an, __shfl_xor_sync(0xffffffffu, an, 8));
                an = fminf(an, __shfl_xor_sync(0xffffffffu, an, 16));
                if (g == 0) {
                    atomicMax(&apSc[col], __float_as_uint(ap));
                    atomicMin(&anSc[col], __float_as_uint(an));
                }
            }
        }
    }
    __syncthreads();
    if (tid < 128) {
        atomicMax(&g_ap[rowBase + tid], apS[tid]);
        atomicMin(&g_an[rowBase + tid], anS[tid]);
        if (bx != by) {
            atomicMax(&g_ap[colBase + tid], apSc[tid]);
            atomicMin(&g_an[colBase + tid], anSc[tid]);
        }
    }
}

// ---------------- centroid (+ fused cc): warp per row ----------------
__global__ void __launch_bounds__(256)
centroid_kernel(const float* __restrict__ X, const int* __restrict__ T) {
    const int warp = threadIdx.x >> 5, lane = threadIdx.x & 31;
    const int i = blockIdx.x * 8 + warp;           // row; grid = 512
    const int c = T[i];
    const float cnt  = (float)g_ccnt[c];
    const float inv1 = 1.f / cnt;
    const float inv2 = 1.f / ((float)N_ROWS - cnt);

    float a1 = 0.f, a2 = 0.f;
    #pragma unroll
    for (int it = 0; it < 4; it++) {
        const int d = (lane + it * 32) * 4;
        const float4 cs = *(const float4*)&g_csum[c * D_DIM + d];
        const float4 x  = *(const float4*)&X[(size_t)i * D_DIM + d];
        const float4 tt = *(const float4*)&g_tot[d];
        float icx = cs.x * inv1 - x.x, icy = cs.y * inv1 - x.y;
        float icz = cs.z * inv1 - x.z, icw = cs.w * inv1 - x.w;
        a1 += icx * icx + icy * icy + icz * icz + icw * icw;
        float ocx = (tt.x - cs.x) * inv2 - x.x, ocy = (tt.y - cs.y) * inv2 - x.y;
        float ocz = (tt.z - cs.z) * inv2 - x.z, ocw = (tt.w - cs.w) * inv2 - x.w;
        a2 += ocx * ocx + ocy * ocy + ocz * ocz + ocw * ocw;
    }
    a1 = warpReduceSum(a1);
    a2 = warpReduceSum(a2);
    if (lane == 0) { g_cp[i] = sqrtf(a1); g_cn[i] = sqrtf(a2); }

    // fused cc: warps owning rows 0..NUM_CL-1 also handle class = row index
    if (i < NUM_CL) {
        const int cnt2 = g_ccnt[i];
        if (cnt2 > 0) {
            const float fc = (float)cnt2;
            const float j1 = 1.f / fc;
            const float j2 = 1.f / ((float)N_ROWS - fc);
            float a = 0.f;
            #pragma unroll
            for (int it = 0; it < 4; it++) {
                const int d = (lane + it * 32) * 4;
                const float4 cs = *(const float4*)&g_csum[i * D_DIM + d];
                const float4 tt = *(const float4*)&g_tot[d];
                float dx = cs.x * j1 - (tt.x - cs.x) * j2;
                float dy = cs.y * j1 - (tt.y - cs.y) * j2;
                float dz = cs.z * j1 - (tt.z - cs.z) * j2;
                float dw = cs.w * j1 - (tt.w - cs.w) * j2;
                a += dx * dx + dy * dy + dz * dz + dw * dw;
            }
            a = warpReduceSum(a);
            if (lane == 0) atomicAdd(&g_cc, fc * sqrtf(a));
        }
    }
}

__global__ void final_kernel(float* __restrict__ out) {
    __shared__ float sh[8];
    float s1 = 0.f, s2 = 0.f;
    for (int i = threadIdx.x; i < N_ROWS; i += 256) {
        float ap = sqrtf(__uint_as_float(g_ap[i]));
        float an = sqrtf(__uint_as_float(g_an[i]));
        s1 += fmaxf(ap - an + MARGIN, 0.f);
        s2 += fmaxf(g_cp[i] - g_cn[i] + MARGIN, 0.f);
    }
    s1 = blockReduceSum(s1, sh);
    __syncthreads();
    s2 = blockReduceSum(s2, sh);
    if (threadIdx.x == 0) {
        out[0] = s1 / (float)N_ROWS;
        out[1] = s2 / (float)N_ROWS;
        out[2] = -g_cc / (float)N_ROWS;
    }
}

// ---------------- entry ----------------
extern "C" void kernel_launch(void* const* d_in, const int* in_sizes, int n_in,
                              void* d_out, int out_size) {
    const float* X = (const float*)d_in[0];
    const int*   T = (const int*)d_in[1];
    float* out = (float*)d_out;

    cudaFuncSetAttribute(dist_mma_kernel,
                         cudaFuncAttributeMaxDynamicSharedMemorySize,
                         NSTG * 2 * STG_BYTES);

    cudaStream_t s2;
    cudaStreamCreateWithFlags(&s2, cudaStreamNonBlocking);
    cudaEvent_t eFork, eJoin;
    cudaEventCreateWithFlags(&eFork, cudaEventDisableTiming);
    cudaEventCreateWithFlags(&eJoin, cudaEventDisableTiming);

    // fork
    cudaEventRecord(eFork, 0);
    cudaStreamWaitEvent(s2, eFork, 0);

    // chain A (origin stream): prep -> dist (PDL edge)
    prep_kernel<<<N_ROWS, 128>>>(X);

    // chain B (side stream): classsum -> tot -> centroid(+cc)
    classsum_kernel<<<NUM_CL, 256, 0, s2>>>(X, T);
    tot_kernel<<<D_DIM, 128, 0, s2>>>();
    centroid_kernel<<<N_ROWS / 8, 256, 0, s2>>>(X, T);
    cudaEventRecord(eJoin, s2);

    // dist with programmatic dependent launch: overlaps its dispatch/setup
    // with prep's tail; griddepcontrol.wait inside guards prep's outputs.
    {
        const int ntiles = NTILE * (NTILE + 1) / 2;        // 528
        cudaLaunchConfig_t cfg = {};
        cfg.gridDim = dim3((unsigned)ntiles, 1, 1);
        cfg.blockDim = dim3(256, 1, 1);
        cfg.dynamicSmemBytes = NSTG * 2 * STG_BYTES;
        cfg.stream = 0;
        cudaLaunchAttribute attrs[1];
        attrs[0].id = cudaLaunchAttributeProgrammaticStreamSerialization;
        attrs[0].val.programmaticStreamSerializationAllowed = 1;
        cfg.attrs = attrs;
        cfg.numAttrs = 1;
        cudaLaunchKernelEx(&cfg, dist_mma_kernel, T);
    }

    // join, then final reduction
    cudaStreamWaitEvent(0, eJoin, 0);
    final_kernel<<<1, 256>>>(out);
}